// round 2
// baseline (speedup 1.0000x reference)
#include <cuda_runtime.h>

#define NN 100000
#define EE 1600000
#define BG 64
#define HD 128
#define DIN 9
#define EPS 1e-5f
#define NB_SCAN 391   // ceil(NN/256)

// ---------------- scratch (static __device__, no allocation) ----------------
__device__ float g_h[2][NN * HD];        // ping-pong node features (2 x 51.2MB)
__device__ float g_agg[NN * HD];         // mean-aggregated features
__device__ float g_WT[3][256 * HD];      // combined transposed weights [Wl^T ; Wr^T]
__device__ int   g_deg[NN];
__device__ int   g_rowptr[NN];
__device__ int   g_cursor[NN];
__device__ int   g_col[EE];
__device__ int   g_bsum[512];
__device__ int   g_boff[512];
__device__ float g_cnt[BG];

// ---------------- weight transpose: WT[l][k][c] ----------------
__global__ void transpose_w(const float* __restrict__ Wl1, const float* __restrict__ Wr1,
                            const float* __restrict__ Wl2, const float* __restrict__ Wr2,
                            const float* __restrict__ Wl3, const float* __restrict__ Wr3) {
    int idx = blockIdx.x * blockDim.x + threadIdx.x;
    if (idx >= 3 * 256 * HD) return;
    int l = idx >> 15;
    int rem = idx & 32767;
    int k = rem >> 7;
    int c = rem & 127;
    const float* Wl = (l == 0) ? Wl1 : (l == 1) ? Wl2 : Wl3;
    const float* Wr = (l == 0) ? Wr1 : (l == 1) ? Wr2 : Wr3;
    float v = (k < HD) ? Wl[c * HD + k] : Wr[c * HD + (k - HD)];
    g_WT[l][k * HD + c] = v;
}

// ---------------- node embedder: h = ReLU(LN(x@W0^T + b0)) ----------------
__global__ void embed_kernel(const float* __restrict__ x, const float* __restrict__ W0,
                             const float* __restrict__ b0, const float* __restrict__ g0,
                             const float* __restrict__ be0) {
    __shared__ float Ws[HD * DIN];
    __shared__ float xs[DIN];
    __shared__ float redS[4], redQ[4];
    int tx = threadIdx.x;  // 128 threads
    for (int i = tx; i < HD * DIN; i += 128) Ws[i] = W0[i];
    float bb = b0[tx], gg = g0[tx], be = be0[tx];
    int node0 = blockIdx.x * 16;
    float* hout = g_h[0];

    for (int nn = 0; nn < 16; nn++) {
        int n = node0 + nn;
        __syncthreads();
        if (n < NN && tx < DIN) xs[tx] = x[n * DIN + tx];
        __syncthreads();
        float v = bb;
        if (n < NN) {
#pragma unroll
            for (int j = 0; j < DIN; j++) v += xs[j] * Ws[tx * DIN + j];
        } else {
            v = 0.f;
        }
        float s = v, s2 = v * v;
#pragma unroll
        for (int o = 16; o; o >>= 1) {
            s += __shfl_xor_sync(0xffffffffu, s, o);
            s2 += __shfl_xor_sync(0xffffffffu, s2, o);
        }
        if ((tx & 31) == 0) { redS[tx >> 5] = s; redQ[tx >> 5] = s2; }
        __syncthreads();
        s  = redS[0] + redS[1] + redS[2] + redS[3];
        s2 = redQ[0] + redQ[1] + redQ[2] + redQ[3];
        float mean = s * (1.f / HD);
        float var = s2 * (1.f / HD) - mean * mean;
        float rstd = rsqrtf(var + EPS);
        if (n < NN) {
            float o = fmaxf((v - mean) * rstd * gg + be, 0.f);
            hout[n * HD + tx] = o;
        }
    }
}

// ---------------- CSR construction ----------------
__global__ void init_deg() {
    int i = blockIdx.x * blockDim.x + threadIdx.x;
    if (i < NN) g_deg[i] = 0;
}
__global__ void count_deg(const int* __restrict__ dst) {
    int e = blockIdx.x * blockDim.x + threadIdx.x;
    if (e < EE) atomicAdd(&g_deg[dst[e]], 1);
}
__global__ void scan1() {
    __shared__ int sm[256];
    int t = threadIdx.x;
    int i = blockIdx.x * 256 + t;
    sm[t] = (i < NN) ? g_deg[i] : 0;
    __syncthreads();
#pragma unroll
    for (int o = 128; o; o >>= 1) {
        if (t < o) sm[t] += sm[t + o];
        __syncthreads();
    }
    if (t == 0) g_bsum[blockIdx.x] = sm[0];
}
__global__ void scan2() {
    __shared__ int sm[512];
    int t = threadIdx.x;
    int v = (t < NB_SCAN) ? g_bsum[t] : 0;
    sm[t] = v;
    __syncthreads();
    for (int o = 1; o < 512; o <<= 1) {
        int add = (t >= o) ? sm[t - o] : 0;
        __syncthreads();
        sm[t] += add;
        __syncthreads();
    }
    if (t < NB_SCAN) g_boff[t] = sm[t] - v;  // exclusive
}
__global__ void scan3() {
    __shared__ int sm[256];
    int t = threadIdx.x;
    int i = blockIdx.x * 256 + t;
    int v = (i < NN) ? g_deg[i] : 0;
    sm[t] = v;
    __syncthreads();
    for (int o = 1; o < 256; o <<= 1) {
        int add = (t >= o) ? sm[t - o] : 0;
        __syncthreads();
        sm[t] += add;
        __syncthreads();
    }
    if (i < NN) {
        int excl = sm[t] - v + g_boff[blockIdx.x];
        g_rowptr[i] = excl;
        g_cursor[i] = excl;
    }
}
__global__ void fill_csr(const int* __restrict__ src, const int* __restrict__ dst) {
    int e = blockIdx.x * blockDim.x + threadIdx.x;
    if (e < EE) {
        int p = atomicAdd(&g_cursor[dst[e]], 1);
        g_col[p] = src[e];
    }
}

// ---------------- mean aggregation: warp per destination node ----------------
__global__ void __launch_bounds__(256) aggregate(int ibuf) {
    int warp = (blockIdx.x * blockDim.x + threadIdx.x) >> 5;
    int lane4 = (threadIdx.x & 31) * 4;
    if (warp >= NN) return;
    const float* __restrict__ h = g_h[ibuf];
    int start = g_rowptr[warp];
    int d = g_deg[warp];
    float4 acc = make_float4(0.f, 0.f, 0.f, 0.f);
    int j = 0;
    for (; j + 3 < d; j += 4) {
        int s0 = g_col[start + j];
        int s1 = g_col[start + j + 1];
        int s2 = g_col[start + j + 2];
        int s3 = g_col[start + j + 3];
        float4 v0 = *(const float4*)(h + s0 * HD + lane4);
        float4 v1 = *(const float4*)(h + s1 * HD + lane4);
        float4 v2 = *(const float4*)(h + s2 * HD + lane4);
        float4 v3 = *(const float4*)(h + s3 * HD + lane4);
        acc.x += v0.x + v1.x + v2.x + v3.x;
        acc.y += v0.y + v1.y + v2.y + v3.y;
        acc.z += v0.z + v1.z + v2.z + v3.z;
        acc.w += v0.w + v1.w + v2.w + v3.w;
    }
    for (; j < d; j++) {
        int s = g_col[start + j];
        float4 v = *(const float4*)(h + s * HD + lane4);
        acc.x += v.x; acc.y += v.y; acc.z += v.z; acc.w += v.w;
    }
    float inv = 1.f / (float)max(d, 1);
    acc.x *= inv; acc.y *= inv; acc.z *= inv; acc.w *= inv;
    *(float4*)(g_agg + warp * HD + lane4) = acc;
}

// ---------------- fused GEMM + bias + LayerNorm + ReLU ----------------
// out[r][c] = ReLU(LN(sum_k agg[r][k]*Wl[c][k] + sum_k h[r][k]*Wr[c][k] + bias[c]))
// K=256 logical (first 128 from agg/Wl, next 128 from h/Wr); WT pre-transposed.
__global__ void __launch_bounds__(256) gemm_fused(
    int ibuf, int layer,
    const float* __restrict__ bias, const float* __restrict__ gamma,
    const float* __restrict__ beta,
    int obuf, float* __restrict__ ext_out) {
    __shared__ float As[16][128];
    __shared__ float Bs[16][128];
    const float* __restrict__ Aagg = g_agg;
    const float* __restrict__ Ah = g_h[ibuf];
    const float* __restrict__ WT = g_WT[layer];
    float* __restrict__ out = ext_out ? ext_out : g_h[obuf];

    int tid = threadIdx.x;
    int tx = tid & 15;         // column group (8 cols each)
    int ty = tid >> 4;         // row group (8 rows each)
    int brow = blockIdx.x * 128;

    float acc[8][8];
#pragma unroll
    for (int i = 0; i < 8; i++)
#pragma unroll
        for (int j = 0; j < 8; j++) acc[i][j] = 0.f;

    for (int kc = 0; kc < 16; kc++) {
        int k0 = kc * 16;
        const float* Ap = (k0 < HD) ? Aagg : Ah;
        int c0 = k0 & 127;
        __syncthreads();
        // stage A: 128 rows x 16 k, stored transposed As[k][row]
#pragma unroll
        for (int it = 0; it < 2; it++) {
            int i = tid + it * 256;
            int row = i >> 2, q = i & 3;
            int grow = brow + row;
            float4 v = make_float4(0.f, 0.f, 0.f, 0.f);
            if (grow < NN) v = *(const float4*)(Ap + grow * HD + c0 + q * 4);
            As[q * 4 + 0][row] = v.x;
            As[q * 4 + 1][row] = v.y;
            As[q * 4 + 2][row] = v.z;
            As[q * 4 + 3][row] = v.w;
        }
        // stage B: 16 k x 128 cols
#pragma unroll
        for (int it = 0; it < 2; it++) {
            int i = tid + it * 256;
            int k = i >> 5, q = i & 31;
            *(float4*)&Bs[k][q * 4] = *(const float4*)(WT + (k0 + k) * HD + q * 4);
        }
        __syncthreads();
#pragma unroll
        for (int k = 0; k < 16; k++) {
            float a[8], b[8];
            *(float4*)(a)     = *(float4*)&As[k][ty * 8];
            *(float4*)(a + 4) = *(float4*)&As[k][ty * 8 + 4];
            *(float4*)(b)     = *(float4*)&Bs[k][tx * 8];
            *(float4*)(b + 4) = *(float4*)&Bs[k][tx * 8 + 4];
#pragma unroll
            for (int i = 0; i < 8; i++)
#pragma unroll
                for (int j = 0; j < 8; j++) acc[i][j] += a[i] * b[j];
        }
    }

    // epilogue: bias + LayerNorm across 128 cols (16 lanes x 8 cols) + ReLU
    float bsv[8], gm[8], bt[8];
#pragma unroll
    for (int j = 0; j < 8; j++) {
        int c = tx * 8 + j;
        bsv[j] = bias[c];
        gm[j] = gamma[c];
        bt[j] = beta[c];
    }
#pragma unroll
    for (int i = 0; i < 8; i++) {
        float s = 0.f, s2 = 0.f;
#pragma unroll
        for (int j = 0; j < 8; j++) {
            float v = acc[i][j] + bsv[j];
            acc[i][j] = v;
            s += v;
            s2 += v * v;
        }
        // reduce across the 16 lanes that hold this row (xor 1,2,4,8 stays in-group)
#pragma unroll
        for (int o = 1; o < 16; o <<= 1) {
            s += __shfl_xor_sync(0xffffffffu, s, o);
            s2 += __shfl_xor_sync(0xffffffffu, s2, o);
        }
        float mean = s * (1.f / HD);
        float var = s2 * (1.f / HD) - mean * mean;
        float rstd = rsqrtf(var + EPS);
        int gr = brow + ty * 8 + i;
        if (gr < NN) {
            float o[8];
#pragma unroll
            for (int j = 0; j < 8; j++)
                o[j] = fmaxf((acc[i][j] - mean) * rstd * gm[j] + bt[j], 0.f);
            *(float4*)(out + gr * HD + tx * 8)     = *(float4*)(o);
            *(float4*)(out + gr * HD + tx * 8 + 4) = *(float4*)(o + 4);
        }
    }
}

// ---------------- pooling ----------------
__global__ void zero_pool(float* __restrict__ gout) {
    int i = blockIdx.x * blockDim.x + threadIdx.x;
    if (i < BG * 2 * HD) gout[i] = 0.f;
    if (i < BG) g_cnt[i] = 0.f;
}
__global__ void count_batch(const int* __restrict__ batch) {
    int i = blockIdx.x * blockDim.x + threadIdx.x;
    if (i < NN) atomicAdd(&g_cnt[batch[i]], 1.f);
}
// batch is sorted: running sum/max per 128-node chunk, flush on segment change.
__global__ void pool_accum(const float* __restrict__ ne, const int* __restrict__ batch,
                           float* __restrict__ gout) {
    int tx = threadIdx.x;  // 128 = column
    int n0 = blockIdx.x * 128;
    int n1 = min(n0 + 128, NN);
    if (n0 >= NN) return;
    int cur = batch[n0];
    float sum = 0.f, mx = 0.f;
    for (int n = n0; n < n1; n++) {
        int b = batch[n];
        float v = ne[n * HD + tx];
        if (b != cur) {
            atomicAdd(&gout[cur * 256 + tx], sum);
            atomicMax((int*)&gout[cur * 256 + HD + tx], __float_as_int(mx));
            sum = 0.f; mx = 0.f; cur = b;
        }
        sum += v;
        mx = fmaxf(mx, v);
    }
    atomicAdd(&gout[cur * 256 + tx], sum);
    atomicMax((int*)&gout[cur * 256 + HD + tx], __float_as_int(mx));
}
__global__ void finalize_pool(float* __restrict__ gout) {
    int b = blockIdx.x;
    int tx = threadIdx.x;
    gout[b * 256 + tx] /= fmaxf(g_cnt[b], 1.f);
}

// ---------------- launch ----------------
extern "C" void kernel_launch(void* const* d_in, const int* in_sizes, int n_in,
                              void* d_out, int out_size) {
    const float* x   = (const float*)d_in[0];
    const int* ei    = (const int*)d_in[1];   // [2,E] row-major: src=ei[0:E], dst=ei[E:2E]
    const int* batch = (const int*)d_in[2];
    const float* W0  = (const float*)d_in[3];
    const float* b0  = (const float*)d_in[4];
    const float* g0  = (const float*)d_in[5];
    const float* be0 = (const float*)d_in[6];
    const float* Wl1 = (const float*)d_in[7];
    const float* bl1 = (const float*)d_in[8];
    const float* Wr1 = (const float*)d_in[9];
    const float* g1  = (const float*)d_in[10];
    const float* be1 = (const float*)d_in[11];
    const float* Wl2 = (const float*)d_in[12];
    const float* bl2 = (const float*)d_in[13];
    const float* Wr2 = (const float*)d_in[14];
    const float* g2  = (const float*)d_in[15];
    const float* be2 = (const float*)d_in[16];
    const float* Wl3 = (const float*)d_in[17];
    const float* bl3 = (const float*)d_in[18];
    const float* Wr3 = (const float*)d_in[19];
    const float* g3  = (const float*)d_in[20];
    const float* be3 = (const float*)d_in[21];

    float* out = (float*)d_out;
    float* ne = out;                           // node_embed (N*H)
    float* gr = out + (size_t)NN * HD;         // graph_embed (B*2H)

    const int* src = ei;
    const int* dst = ei + EE;

    transpose_w<<<384, 256>>>(Wl1, Wr1, Wl2, Wr2, Wl3, Wr3);
    embed_kernel<<<(NN + 15) / 16, 128>>>(x, W0, b0, g0, be0);

    init_deg<<<NB_SCAN, 256>>>();
    count_deg<<<(EE + 255) / 256, 256>>>(dst);
    scan1<<<NB_SCAN, 256>>>();
    scan2<<<1, 512>>>();
    scan3<<<NB_SCAN, 256>>>();
    fill_csr<<<(EE + 255) / 256, 256>>>(src, dst);

    int gemm_blocks = (NN + 127) / 128;
    int agg_blocks = (NN * 32 + 255) / 256;

    // layer 1: h0 -> h1
    aggregate<<<agg_blocks, 256>>>(0);
    gemm_fused<<<gemm_blocks, 256>>>(0, 0, bl1, g1, be1, 1, nullptr);
    // layer 2: h1 -> h0
    aggregate<<<agg_blocks, 256>>>(1);
    gemm_fused<<<gemm_blocks, 256>>>(1, 1, bl2, g2, be2, 0, nullptr);
    // layer 3: h0 -> d_out node region
    aggregate<<<agg_blocks, 256>>>(0);
    gemm_fused<<<gemm_blocks, 256>>>(0, 2, bl3, g3, be3, 0, ne);

    zero_pool<<<(BG * 2 * HD + 255) / 256, 256>>>(gr);
    count_batch<<<NB_SCAN, 256>>>(batch);
    pool_accum<<<(NN + 127) / 128, 128>>>(ne, batch, gr);
    finalize_pool<<<BG, 128>>>(gr);
}

// round 5
// speedup vs baseline: 1.1327x; 1.1327x over previous
#include <cuda_runtime.h>
#include <cstdint>

#define NN 100000
#define EE 1600000
#define BG 64
#define HD 128
#define DIN 9
#define EPS 1e-5f
#define NB_SCAN 391   // ceil(NN/256)

// ---------------- scratch (static __device__, no allocation) ----------------
__device__ float g_h[2][NN * HD];        // ping-pong node features
__device__ float g_agg[NN * HD];         // mean-aggregated features
__device__ float g_WT[3][256 * HD];      // combined transposed weights [Wl^T ; Wr^T], [k][c]
__device__ int   g_deg[NN];
__device__ int   g_rowptr[NN];
__device__ int   g_cursor[NN];
__device__ int   g_col[EE];
__device__ int   g_bsum[512];
__device__ int   g_boff[512];
__device__ float g_cnt[BG];

// ---------------- tf32 helpers ----------------
__device__ __forceinline__ uint32_t f2tf32(float x) {
    uint32_t r;
    asm("cvt.rna.tf32.f32 %0, %1;" : "=r"(r) : "f"(x));
    return r;
}
__device__ __forceinline__ void split_tf32(float x, float& hi, float& lo) {
    hi = __uint_as_float(f2tf32(x));
    lo = __uint_as_float(f2tf32(x - hi));
}
__device__ __forceinline__ void mma_tf32(float* c, uint32_t a0, uint32_t a1,
                                         uint32_t a2, uint32_t a3,
                                         uint32_t b0, uint32_t b1) {
    asm volatile(
        "mma.sync.aligned.m16n8k8.row.col.f32.tf32.tf32.f32 "
        "{%0,%1,%2,%3},{%4,%5,%6,%7},{%8,%9},{%0,%1,%2,%3};\n"
        : "+f"(c[0]), "+f"(c[1]), "+f"(c[2]), "+f"(c[3])
        : "r"(a0), "r"(a1), "r"(a2), "r"(a3), "r"(b0), "r"(b1));
}

// ---------------- weight transpose: WT[l][k][c] ----------------
__global__ void transpose_w(const float* __restrict__ Wl1, const float* __restrict__ Wr1,
                            const float* __restrict__ Wl2, const float* __restrict__ Wr2,
                            const float* __restrict__ Wl3, const float* __restrict__ Wr3) {
    int idx = blockIdx.x * blockDim.x + threadIdx.x;
    if (idx >= 3 * 256 * HD) return;
    int l = idx >> 15;
    int rem = idx & 32767;
    int k = rem >> 7;
    int c = rem & 127;
    const float* Wl = (l == 0) ? Wl1 : (l == 1) ? Wl2 : Wl3;
    const float* Wr = (l == 0) ? Wr1 : (l == 1) ? Wr2 : Wr3;
    float v = (k < HD) ? Wl[c * HD + k] : Wr[c * HD + (k - HD)];
    g_WT[l][k * HD + c] = v;
}

// ---------------- node embedder: h = ReLU(LN(x@W0^T + b0)) ----------------
__global__ void embed_kernel(const float* __restrict__ x, const float* __restrict__ W0,
                             const float* __restrict__ b0, const float* __restrict__ g0,
                             const float* __restrict__ be0) {
    __shared__ float Ws[HD * DIN];
    __shared__ float xs[DIN];
    __shared__ float redS[4], redQ[4];
    int tx = threadIdx.x;  // 128 threads
    for (int i = tx; i < HD * DIN; i += 128) Ws[i] = W0[i];
    float bb = b0[tx], gg = g0[tx], be = be0[tx];
    int node0 = blockIdx.x * 16;
    float* hout = g_h[0];

    for (int nn = 0; nn < 16; nn++) {
        int n = node0 + nn;
        __syncthreads();
        if (n < NN && tx < DIN) xs[tx] = x[n * DIN + tx];
        __syncthreads();
        float v = bb;
        if (n < NN) {
#pragma unroll
            for (int j = 0; j < DIN; j++) v += xs[j] * Ws[tx * DIN + j];
        } else {
            v = 0.f;
        }
        float s = v, s2 = v * v;
#pragma unroll
        for (int o = 16; o; o >>= 1) {
            s += __shfl_xor_sync(0xffffffffu, s, o);
            s2 += __shfl_xor_sync(0xffffffffu, s2, o);
        }
        if ((tx & 31) == 0) { redS[tx >> 5] = s; redQ[tx >> 5] = s2; }
        __syncthreads();
        s  = redS[0] + redS[1] + redS[2] + redS[3];
        s2 = redQ[0] + redQ[1] + redQ[2] + redQ[3];
        float mean = s * (1.f / HD);
        float var = s2 * (1.f / HD) - mean * mean;
        float rstd = rsqrtf(var + EPS);
        if (n < NN) {
            float o = fmaxf((v - mean) * rstd * gg + be, 0.f);
            hout[n * HD + tx] = o;
        }
    }
}

// ---------------- CSR construction ----------------
__global__ void init_deg() {
    int i = blockIdx.x * blockDim.x + threadIdx.x;
    if (i < NN) g_deg[i] = 0;
}
__global__ void count_deg(const int* __restrict__ dst) {
    int e = blockIdx.x * blockDim.x + threadIdx.x;
    if (e < EE) atomicAdd(&g_deg[dst[e]], 1);
}
__global__ void scan1() {
    __shared__ int sm[256];
    int t = threadIdx.x;
    int i = blockIdx.x * 256 + t;
    sm[t] = (i < NN) ? g_deg[i] : 0;
    __syncthreads();
#pragma unroll
    for (int o = 128; o; o >>= 1) {
        if (t < o) sm[t] += sm[t + o];
        __syncthreads();
    }
    if (t == 0) g_bsum[blockIdx.x] = sm[0];
}
__global__ void scan2() {
    __shared__ int sm[512];
    int t = threadIdx.x;
    int v = (t < NB_SCAN) ? g_bsum[t] : 0;
    sm[t] = v;
    __syncthreads();
    for (int o = 1; o < 512; o <<= 1) {
        int add = (t >= o) ? sm[t - o] : 0;
        __syncthreads();
        sm[t] += add;
        __syncthreads();
    }
    if (t < NB_SCAN) g_boff[t] = sm[t] - v;  // exclusive
}
__global__ void scan3() {
    __shared__ int sm[256];
    int t = threadIdx.x;
    int i = blockIdx.x * 256 + t;
    int v = (i < NN) ? g_deg[i] : 0;
    sm[t] = v;
    __syncthreads();
    for (int o = 1; o < 256; o <<= 1) {
        int add = (t >= o) ? sm[t - o] : 0;
        __syncthreads();
        sm[t] += add;
        __syncthreads();
    }
    if (i < NN) {
        int excl = sm[t] - v + g_boff[blockIdx.x];
        g_rowptr[i] = excl;
        g_cursor[i] = excl;
    }
}
__global__ void fill_csr(const int* __restrict__ src, const int* __restrict__ dst) {
    int e = blockIdx.x * blockDim.x + threadIdx.x;
    if (e < EE) {
        int p = atomicAdd(&g_cursor[dst[e]], 1);
        g_col[p] = src[e];
    }
}

// ---------------- mean aggregation: warp per destination node ----------------
__global__ void __launch_bounds__(256) aggregate(int ibuf) {
    int warp = (blockIdx.x * blockDim.x + threadIdx.x) >> 5;
    int lane4 = (threadIdx.x & 31) * 4;
    if (warp >= NN) return;
    const float* __restrict__ h = g_h[ibuf];
    int start = g_rowptr[warp];
    int d = g_deg[warp];
    float4 acc = make_float4(0.f, 0.f, 0.f, 0.f);
    int j = 0;
    for (; j + 3 < d; j += 4) {
        int s0 = g_col[start + j];
        int s1 = g_col[start + j + 1];
        int s2 = g_col[start + j + 2];
        int s3 = g_col[start + j + 3];
        float4 v0 = *(const float4*)(h + s0 * HD + lane4);
        float4 v1 = *(const float4*)(h + s1 * HD + lane4);
        float4 v2 = *(const float4*)(h + s2 * HD + lane4);
        float4 v3 = *(const float4*)(h + s3 * HD + lane4);
        acc.x += v0.x + v1.x + v2.x + v3.x;
        acc.y += v0.y + v1.y + v2.y + v3.y;
        acc.z += v0.z + v1.z + v2.z + v3.z;
        acc.w += v0.w + v1.w + v2.w + v3.w;
    }
    for (; j < d; j++) {
        int s = g_col[start + j];
        float4 v = *(const float4*)(h + s * HD + lane4);
        acc.x += v.x; acc.y += v.y; acc.z += v.z; acc.w += v.w;
    }
    float inv = 1.f / (float)max(d, 1);
    acc.x *= inv; acc.y *= inv; acc.z *= inv; acc.w *= inv;
    *(float4*)(g_agg + warp * HD + lane4) = acc;
}

// ---------------- tensor-core tf32 GEMM + bias + LayerNorm + ReLU ----------------
// Block: 256 rows x 128 cols, 8 warps of 64x64. K=256 (agg|h vs [Wl^T;Wr^T]).
// 3-term tf32 split: Ah*Bh + Al*Bh + Ah*Bl (fp32-accurate).
// Dynamic smem layout (floats):
//   As_hi[256][36], As_lo[256][36]   (stride 36 -> conflict-free frag LDS)
//   Bs_hi[32][136], Bs_lo[32][136]   (stride 136)
//   bias[128], gamma[128], beta[128]
//   red[256][2][2]
#define AS_STRIDE 36
#define BS_STRIDE 136
#define OFF_ASLO   (256 * AS_STRIDE)
#define OFF_BSHI   (2 * 256 * AS_STRIDE)
#define OFF_BSLO   (OFF_BSHI + 32 * BS_STRIDE)
#define OFF_BIAS   (OFF_BSHI + 2 * 32 * BS_STRIDE)
#define OFF_GAMMA  (OFF_BIAS + 128)
#define OFF_BETA   (OFF_GAMMA + 128)
#define OFF_RED    (OFF_BETA + 128)
#define SMEM_FLOATS (OFF_RED + 256 * 4)

__global__ void __launch_bounds__(256) gemm_fused_tc(
    int ibuf, int layer,
    const float* __restrict__ bias, const float* __restrict__ gamma,
    const float* __restrict__ beta,
    int obuf, float* __restrict__ ext_out) {
    extern __shared__ float sm[];
    float* As_hi = sm;
    float* As_lo = sm + OFF_ASLO;
    float* Bs_hi = sm + OFF_BSHI;
    float* Bs_lo = sm + OFF_BSLO;
    float* bias_s = sm + OFF_BIAS;
    float* gamma_s = sm + OFF_GAMMA;
    float* beta_s = sm + OFF_BETA;
    float* red = sm + OFF_RED;

    const float* __restrict__ WT = g_WT[layer];
    float* __restrict__ out = ext_out ? ext_out : g_h[obuf];

    int tid = threadIdx.x;
    int lane = tid & 31;
    int warp = tid >> 5;
    int g = lane >> 2;
    int t = lane & 3;
    int wrow = (warp >> 1) * 64;   // 4 warp-rows
    int wcol = (warp & 1) * 64;    // 2 warp-cols
    int brow = blockIdx.x * 256;

    if (tid < 128) {
        bias_s[tid] = bias[tid];
        gamma_s[tid] = gamma[tid];
        beta_s[tid] = beta[tid];
    }

    float acc[4][8][4];
#pragma unroll
    for (int mi = 0; mi < 4; mi++)
#pragma unroll
        for (int ni = 0; ni < 8; ni++)
#pragma unroll
            for (int c = 0; c < 4; c++) acc[mi][ni][c] = 0.f;

    for (int kc = 0; kc < 8; kc++) {
        int k0g = kc * 32;
        const float* __restrict__ Ap = (k0g < HD) ? g_agg : g_h[ibuf];
        int col0 = k0g & 127;
        __syncthreads();
        // stage A: 256 rows x 32 k
#pragma unroll
        for (int it = 0; it < 8; it++) {
            int i = tid + it * 256;
            int row = i >> 3, kq = i & 7;
            int grow = brow + row;
            float4 v = make_float4(0.f, 0.f, 0.f, 0.f);
            if (grow < NN) v = *(const float4*)(Ap + grow * HD + col0 + kq * 4);
            float4 hi, lo;
            split_tf32(v.x, hi.x, lo.x);
            split_tf32(v.y, hi.y, lo.y);
            split_tf32(v.z, hi.z, lo.z);
            split_tf32(v.w, hi.w, lo.w);
            *(float4*)(As_hi + row * AS_STRIDE + kq * 4) = hi;
            *(float4*)(As_lo + row * AS_STRIDE + kq * 4) = lo;
        }
        // stage B: 32 k x 128 cols
#pragma unroll
        for (int it = 0; it < 4; it++) {
            int i = tid + it * 256;
            int k = i >> 5, cq = i & 31;
            float4 v = *(const float4*)(WT + (k0g + k) * HD + cq * 4);
            float4 hi, lo;
            split_tf32(v.x, hi.x, lo.x);
            split_tf32(v.y, hi.y, lo.y);
            split_tf32(v.z, hi.z, lo.z);
            split_tf32(v.w, hi.w, lo.w);
            *(float4*)(Bs_hi + k * BS_STRIDE + cq * 4) = hi;
            *(float4*)(Bs_lo + k * BS_STRIDE + cq * 4) = lo;
        }
        __syncthreads();

#pragma unroll
        for (int ks = 0; ks < 4; ks++) {
            int k0 = ks * 8;
            uint32_t ah[4][4], al[4][4], bh[8][2], bl[8][2];
#pragma unroll
            for (int mi = 0; mi < 4; mi++) {
                int r0 = (wrow + mi * 16 + g) * AS_STRIDE;
                ah[mi][0] = __float_as_uint(As_hi[r0 + k0 + t]);
                ah[mi][1] = __float_as_uint(As_hi[r0 + 8 * AS_STRIDE + k0 + t]);
                ah[mi][2] = __float_as_uint(As_hi[r0 + k0 + t + 4]);
                ah[mi][3] = __float_as_uint(As_hi[r0 + 8 * AS_STRIDE + k0 + t + 4]);
                al[mi][0] = __float_as_uint(As_lo[r0 + k0 + t]);
                al[mi][1] = __float_as_uint(As_lo[r0 + 8 * AS_STRIDE + k0 + t]);
                al[mi][2] = __float_as_uint(As_lo[r0 + k0 + t + 4]);
                al[mi][3] = __float_as_uint(As_lo[r0 + 8 * AS_STRIDE + k0 + t + 4]);
            }
#pragma unroll
            for (int ni = 0; ni < 8; ni++) {
                int c0 = wcol + ni * 8 + g;
                bh[ni][0] = __float_as_uint(Bs_hi[(k0 + t) * BS_STRIDE + c0]);
                bh[ni][1] = __float_as_uint(Bs_hi[(k0 + t + 4) * BS_STRIDE + c0]);
                bl[ni][0] = __float_as_uint(Bs_lo[(k0 + t) * BS_STRIDE + c0]);
                bl[ni][1] = __float_as_uint(Bs_lo[(k0 + t + 4) * BS_STRIDE + c0]);
            }
#pragma unroll
            for (int mi = 0; mi < 4; mi++)
#pragma unroll
                for (int ni = 0; ni < 8; ni++) {
                    mma_tf32(acc[mi][ni], ah[mi][0], ah[mi][1], ah[mi][2], ah[mi][3],
                             bh[ni][0], bh[ni][1]);
                    mma_tf32(acc[mi][ni], al[mi][0], al[mi][1], al[mi][2], al[mi][3],
                             bh[ni][0], bh[ni][1]);
                    mma_tf32(acc[mi][ni], ah[mi][0], ah[mi][1], ah[mi][2], ah[mi][3],
                             bl[ni][0], bl[ni][1]);
                }
        }
    }
    __syncthreads();   // done with staging smem; safe to reuse red region

    // ---- epilogue: bias + LN(128 cols) + ReLU ----
    // add bias into acc; per-thread partials per (mi, half)
    float ps[4][2], pq[4][2];
#pragma unroll
    for (int mi = 0; mi < 4; mi++)
#pragma unroll
        for (int h = 0; h < 2; h++) { ps[mi][h] = 0.f; pq[mi][h] = 0.f; }
#pragma unroll
    for (int mi = 0; mi < 4; mi++)
#pragma unroll
        for (int ni = 0; ni < 8; ni++) {
            int cbase = wcol + ni * 8 + 2 * t;
            float b0v = bias_s[cbase], b1v = bias_s[cbase + 1];
            float v;
            v = acc[mi][ni][0] + b0v; acc[mi][ni][0] = v; ps[mi][0] += v; pq[mi][0] += v * v;
            v = acc[mi][ni][1] + b1v; acc[mi][ni][1] = v; ps[mi][0] += v; pq[mi][0] += v * v;
            v = acc[mi][ni][2] + b0v; acc[mi][ni][2] = v; ps[mi][1] += v; pq[mi][1] += v * v;
            v = acc[mi][ni][3] + b1v; acc[mi][ni][3] = v; ps[mi][1] += v; pq[mi][1] += v * v;
        }
    // reduce across the 4 lanes sharing a row (xor 1,2)
#pragma unroll
    for (int mi = 0; mi < 4; mi++)
#pragma unroll
        for (int h = 0; h < 2; h++) {
#pragma unroll
            for (int o = 1; o < 4; o <<= 1) {
                ps[mi][h] += __shfl_xor_sync(0xffffffffu, ps[mi][h], o);
                pq[mi][h] += __shfl_xor_sync(0xffffffffu, pq[mi][h], o);
            }
        }
    // cross-warp (2 warp-cols) via smem
    if (t == 0) {
#pragma unroll
        for (int mi = 0; mi < 4; mi++)
#pragma unroll
            for (int h = 0; h < 2; h++) {
                int rl = wrow + mi * 16 + h * 8 + g;
                red[rl * 4 + (warp & 1) * 2 + 0] = ps[mi][h];
                red[rl * 4 + (warp & 1) * 2 + 1] = pq[mi][h];
            }
    }
    __syncthreads();
#pragma unroll
    for (int mi = 0; mi < 4; mi++)
#pragma unroll
        for (int h = 0; h < 2; h++) {
            int rl = wrow + mi * 16 + h * 8 + g;
            float S = red[rl * 4 + 0] + red[rl * 4 + 2];
            float Q = red[rl * 4 + 1] + red[rl * 4 + 3];
            float mean = S * (1.f / HD);
            float var = Q * (1.f / HD) - mean * mean;
            float rstd = rsqrtf(var + EPS);
            int grow = brow + rl;
            if (grow < NN) {
#pragma unroll
                for (int ni = 0; ni < 8; ni++) {
                    int cbase = wcol + ni * 8 + 2 * t;
                    float v0 = acc[mi][ni][h * 2 + 0];
                    float v1 = acc[mi][ni][h * 2 + 1];
                    float o0 = fmaxf((v0 - mean) * rstd * gamma_s[cbase] + beta_s[cbase], 0.f);
                    float o1 = fmaxf((v1 - mean) * rstd * gamma_s[cbase + 1] + beta_s[cbase + 1], 0.f);
                    float2 o2 = make_float2(o0, o1);
                    *(float2*)(out + grow * HD + cbase) = o2;
                }
            }
        }
}

// ---------------- pooling ----------------
__global__ void zero_pool(float* __restrict__ gout) {
    int i = blockIdx.x * blockDim.x + threadIdx.x;
    if (i < BG * 2 * HD) gout[i] = 0.f;
    if (i < BG) g_cnt[i] = 0.f;
}
__global__ void count_batch(const int* __restrict__ batch) {
    int i = blockIdx.x * blockDim.x + threadIdx.x;
    if (i < NN) atomicAdd(&g_cnt[batch[i]], 1.f);
}
__global__ void pool_accum(const float* __restrict__ ne, const int* __restrict__ batch,
                           float* __restrict__ gout) {
    int tx = threadIdx.x;  // 128 = column
    int n0 = blockIdx.x * 128;
    int n1 = min(n0 + 128, NN);
    if (n0 >= NN) return;
    int cur = batch[n0];
    float sum = 0.f, mx = 0.f;
    for (int n = n0; n < n1; n++) {
        int b = batch[n];
        float v = ne[n * HD + tx];
        if (b != cur) {
            atomicAdd(&gout[cur * 256 + tx], sum);
            atomicMax((int*)&gout[cur * 256 + HD + tx], __float_as_int(mx));
            sum = 0.f; mx = 0.f; cur = b;
        }
        sum += v;
        mx = fmaxf(mx, v);
    }
    atomicAdd(&gout[cur * 256 + tx], sum);
    atomicMax((int*)&gout[cur * 256 + HD + tx], __float_as_int(mx));
}
__global__ void finalize_pool(float* __restrict__ gout) {
    int b = blockIdx.x;
    int tx = threadIdx.x;
    gout[b * 256 + tx] /= fmaxf(g_cnt[b], 1.f);
}

// ---------------- launch ----------------
extern "C" void kernel_launch(void* const* d_in, const int* in_sizes, int n_in,
                              void* d_out, int out_size) {
    const float* x   = (const float*)d_in[0];
    const int* ei    = (const int*)d_in[1];
    const int* batch = (const int*)d_in[2];
    const float* W0  = (const float*)d_in[3];
    const float* b0  = (const float*)d_in[4];
    const float* g0  = (const float*)d_in[5];
    const float* be0 = (const float*)d_in[6];
    const float* Wl1 = (const float*)d_in[7];
    const float* bl1 = (const float*)d_in[8];
    const float* Wr1 = (const float*)d_in[9];
    const float* g1  = (const float*)d_in[10];
    const float* be1 = (const float*)d_in[11];
    const float* Wl2 = (const float*)d_in[12];
    const float* bl2 = (const float*)d_in[13];
    const float* Wr2 = (const float*)d_in[14];
    const float* g2  = (const float*)d_in[15];
    const float* be2 = (const float*)d_in[16];
    const float* Wl3 = (const float*)d_in[17];
    const float* bl3 = (const float*)d_in[18];
    const float* Wr3 = (const float*)d_in[19];
    const float* g3  = (const float*)d_in[20];
    const float* be3 = (const float*)d_in[21];

    float* out = (float*)d_out;
    float* ne = out;                           // node_embed (N*H)
    float* gr = out + (size_t)NN * HD;         // graph_embed (B*2H)

    const int* src = ei;
    const int* dst = ei + EE;

    static int smem_set = 0;
    size_t smemSz = SMEM_FLOATS * sizeof(float);
    if (!smem_set) {
        cudaFuncSetAttribute(gemm_fused_tc, cudaFuncAttributeMaxDynamicSharedMemorySize,
                             (int)smemSz);
        smem_set = 1;
    }

    transpose_w<<<384, 256>>>(Wl1, Wr1, Wl2, Wr2, Wl3, Wr3);
    embed_kernel<<<(NN + 15) / 16, 128>>>(x, W0, b0, g0, be0);

    init_deg<<<NB_SCAN, 256>>>();
    count_deg<<<(EE + 255) / 256, 256>>>(dst);
    scan1<<<NB_SCAN, 256>>>();
    scan2<<<1, 512>>>();
    scan3<<<NB_SCAN, 256>>>();
    fill_csr<<<(EE + 255) / 256, 256>>>(src, dst);

    int gemm_blocks = (NN + 255) / 256;
    int agg_blocks = (NN * 32 + 255) / 256;

    // layer 1: h0 -> h1
    aggregate<<<agg_blocks, 256>>>(0);
    gemm_fused_tc<<<gemm_blocks, 256, smemSz>>>(0, 0, bl1, g1, be1, 1, nullptr);
    // layer 2: h1 -> h0
    aggregate<<<agg_blocks, 256>>>(1);
    gemm_fused_tc<<<gemm_blocks, 256, smemSz>>>(1, 1, bl2, g2, be2, 0, nullptr);
    // layer 3: h0 -> d_out node region
    aggregate<<<agg_blocks, 256>>>(0);
    gemm_fused_tc<<<gemm_blocks, 256, smemSz>>>(0, 2, bl3, g3, be3, 0, ne);

    zero_pool<<<(BG * 2 * HD + 255) / 256, 256>>>(gr);
    count_batch<<<NB_SCAN, 256>>>(batch);
    pool_accum<<<(NN + 127) / 128, 128>>>(ne, batch, gr);
    finalize_pool<<<BG, 128>>>(gr);
}

// round 6
// speedup vs baseline: 1.2983x; 1.1462x over previous
#include <cuda_runtime.h>
#include <cuda_bf16.h>
#include <cstdint>

#define NN 100000
#define EE 1600000
#define BG 64
#define HD 128
#define DIN 9
#define EPS 1e-5f
#define NB_SCAN 391   // ceil(NN/256)

// ---------------- scratch (static __device__, no allocation) ----------------
__device__ float g_h[2][NN * HD];        // ping-pong node features
__device__ float g_agg[NN * HD];         // mean-aggregated features
__device__ int   g_deg[NN];
__device__ int   g_rowptr[NN];
__device__ int   g_cursor[NN];
__device__ int   g_col[EE];
__device__ int   g_bsum[512];
__device__ int   g_boff[512];
__device__ float g_cnt[BG];

// ---------------- bf16 helpers ----------------
__device__ __forceinline__ uint32_t pack2(float a, float b) {
    __nv_bfloat162 t = __floats2bfloat162_rn(a, b);  // .x = a (low 16 bits)
    return *(uint32_t*)&t;
}
__device__ __forceinline__ void split2(float x, float& hi, float& lo) {
    hi = __bfloat162float(__float2bfloat16(x));
    lo = x - hi;
}
__device__ __forceinline__ void mma_bf16(float* c, uint32_t a0, uint32_t a1,
                                         uint32_t a2, uint32_t a3,
                                         uint32_t b0, uint32_t b1) {
    asm volatile(
        "mma.sync.aligned.m16n8k16.row.col.f32.bf16.bf16.f32 "
        "{%0,%1,%2,%3},{%4,%5,%6,%7},{%8,%9},{%0,%1,%2,%3};\n"
        : "+f"(c[0]), "+f"(c[1]), "+f"(c[2]), "+f"(c[3])
        : "r"(a0), "r"(a1), "r"(a2), "r"(a3), "r"(b0), "r"(b1));
}

// ---------------- node embedder: h = ReLU(LN(x@W0^T + b0)) ----------------
__global__ void embed_kernel(const float* __restrict__ x, const float* __restrict__ W0,
                             const float* __restrict__ b0, const float* __restrict__ g0,
                             const float* __restrict__ be0) {
    __shared__ float Ws[HD * DIN];
    __shared__ float xs[DIN];
    __shared__ float redS[4], redQ[4];
    int tx = threadIdx.x;  // 128 threads
    for (int i = tx; i < HD * DIN; i += 128) Ws[i] = W0[i];
    float bb = b0[tx], gg = g0[tx], be = be0[tx];
    int node0 = blockIdx.x * 16;
    float* hout = g_h[0];

    for (int nn = 0; nn < 16; nn++) {
        int n = node0 + nn;
        __syncthreads();
        if (n < NN && tx < DIN) xs[tx] = x[n * DIN + tx];
        __syncthreads();
        float v = bb;
        if (n < NN) {
#pragma unroll
            for (int j = 0; j < DIN; j++) v += xs[j] * Ws[tx * DIN + j];
        } else {
            v = 0.f;
        }
        float s = v, s2 = v * v;
#pragma unroll
        for (int o = 16; o; o >>= 1) {
            s += __shfl_xor_sync(0xffffffffu, s, o);
            s2 += __shfl_xor_sync(0xffffffffu, s2, o);
        }
        if ((tx & 31) == 0) { redS[tx >> 5] = s; redQ[tx >> 5] = s2; }
        __syncthreads();
        s  = redS[0] + redS[1] + redS[2] + redS[3];
        s2 = redQ[0] + redQ[1] + redQ[2] + redQ[3];
        float mean = s * (1.f / HD);
        float var = s2 * (1.f / HD) - mean * mean;
        float rstd = rsqrtf(var + EPS);
        if (n < NN) {
            float o = fmaxf((v - mean) * rstd * gg + be, 0.f);
            hout[n * HD + tx] = o;
        }
    }
}

// ---------------- CSR construction ----------------
__global__ void init_deg() {
    int i = blockIdx.x * blockDim.x + threadIdx.x;
    if (i < NN) g_deg[i] = 0;
}
__global__ void count_deg(const int* __restrict__ dst) {
    int e = blockIdx.x * blockDim.x + threadIdx.x;
    if (e < EE) atomicAdd(&g_deg[dst[e]], 1);
}
__global__ void scan1() {
    __shared__ int sm[256];
    int t = threadIdx.x;
    int i = blockIdx.x * 256 + t;
    sm[t] = (i < NN) ? g_deg[i] : 0;
    __syncthreads();
#pragma unroll
    for (int o = 128; o; o >>= 1) {
        if (t < o) sm[t] += sm[t + o];
        __syncthreads();
    }
    if (t == 0) g_bsum[blockIdx.x] = sm[0];
}
__global__ void scan2() {
    __shared__ int sm[512];
    int t = threadIdx.x;
    int v = (t < NB_SCAN) ? g_bsum[t] : 0;
    sm[t] = v;
    __syncthreads();
    for (int o = 1; o < 512; o <<= 1) {
        int add = (t >= o) ? sm[t - o] : 0;
        __syncthreads();
        sm[t] += add;
        __syncthreads();
    }
    if (t < NB_SCAN) g_boff[t] = sm[t] - v;  // exclusive
}
__global__ void scan3() {
    __shared__ int sm[256];
    int t = threadIdx.x;
    int i = blockIdx.x * 256 + t;
    int v = (i < NN) ? g_deg[i] : 0;
    sm[t] = v;
    __syncthreads();
    for (int o = 1; o < 256; o <<= 1) {
        int add = (t >= o) ? sm[t - o] : 0;
        __syncthreads();
        sm[t] += add;
        __syncthreads();
    }
    if (i < NN) {
        int excl = sm[t] - v + g_boff[blockIdx.x];
        g_rowptr[i] = excl;
        g_cursor[i] = excl;
    }
}
__global__ void fill_csr(const int* __restrict__ src, const int* __restrict__ dst) {
    int e = blockIdx.x * blockDim.x + threadIdx.x;
    if (e < EE) {
        int p = atomicAdd(&g_cursor[dst[e]], 1);
        g_col[p] = src[e];
    }
}

// ---------------- mean aggregation: warp per destination node ----------------
__global__ void __launch_bounds__(256) aggregate(int ibuf) {
    int warp = (blockIdx.x * blockDim.x + threadIdx.x) >> 5;
    int lane4 = (threadIdx.x & 31) * 4;
    if (warp >= NN) return;
    const float* __restrict__ h = g_h[ibuf];
    int start = g_rowptr[warp];
    int d = g_deg[warp];
    float4 acc = make_float4(0.f, 0.f, 0.f, 0.f);
    int j = 0;
    for (; j + 3 < d; j += 4) {
        int s0 = g_col[start + j];
        int s1 = g_col[start + j + 1];
        int s2 = g_col[start + j + 2];
        int s3 = g_col[start + j + 3];
        float4 v0 = *(const float4*)(h + s0 * HD + lane4);
        float4 v1 = *(const float4*)(h + s1 * HD + lane4);
        float4 v2 = *(const float4*)(h + s2 * HD + lane4);
        float4 v3 = *(const float4*)(h + s3 * HD + lane4);
        acc.x += v0.x + v1.x + v2.x + v3.x;
        acc.y += v0.y + v1.y + v2.y + v3.y;
        acc.z += v0.z + v1.z + v2.z + v3.z;
        acc.w += v0.w + v1.w + v2.w + v3.w;
    }
    for (; j < d; j++) {
        int s = g_col[start + j];
        float4 v = *(const float4*)(h + s * HD + lane4);
        acc.x += v.x; acc.y += v.y; acc.z += v.z; acc.w += v.w;
    }
    float inv = 1.f / (float)max(d, 1);
    acc.x *= inv; acc.y *= inv; acc.z *= inv; acc.w *= inv;
    *(float4*)(g_agg + warp * HD + lane4) = acc;
}

// ---------------- bf16 split tensor-core GEMM + bias + LayerNorm + ReLU ----------------
// Block: 128 rows x 128 cols. 8 warps as 4x2, warptile 32x64.
// K = 256 logical (k<128: A=g_agg, B=Wl; k>=128: A=h, B=Wr). B read directly from
// Wl/Wr ([c][k] row-major == n-major k-contiguous, exactly the mma B "col" layout).
// 3-term bf16 split: Ah*Bh + Al*Bh + Ah*Bl  (~1.5e-5 relative error).
// smem per 32-k chunk, padded stride 20 words (40 bf16) -> conflict-free frag LDS.
#define KPW 20   // uint32 words per row per 32-k chunk

__global__ void __launch_bounds__(256) gemm_fused_bf16(
    int ibuf,
    const float* __restrict__ Wl, const float* __restrict__ Wr,
    const float* __restrict__ bias, const float* __restrict__ gamma,
    const float* __restrict__ beta,
    int obuf, float* __restrict__ ext_out) {
    __shared__ uint32_t As_hi[128 * KPW], As_lo[128 * KPW];
    __shared__ uint32_t Bs_hi[128 * KPW], Bs_lo[128 * KPW];
    __shared__ float bias_s[128], gamma_s[128], beta_s[128];
    __shared__ float red[128 * 4];

    float* __restrict__ out = ext_out ? ext_out : g_h[obuf];

    int tid = threadIdx.x;
    int lane = tid & 31;
    int warp = tid >> 5;
    int g = lane >> 2;
    int t = lane & 3;
    int wrow = (warp >> 1) * 32;   // 4 warp-rows of 32
    int wcol = (warp & 1) * 64;    // 2 warp-cols of 64
    int brow = blockIdx.x * 128;

    if (tid < 128) {
        bias_s[tid] = bias[tid];
        gamma_s[tid] = gamma[tid];
        beta_s[tid] = beta[tid];
    }

    float acc[2][8][4];
#pragma unroll
    for (int mi = 0; mi < 2; mi++)
#pragma unroll
        for (int ni = 0; ni < 8; ni++)
#pragma unroll
            for (int c = 0; c < 4; c++) acc[mi][ni][c] = 0.f;

    for (int kc = 0; kc < 8; kc++) {
        int k0g = kc * 32;
        const float* __restrict__ Ap = (k0g < HD) ? g_agg : g_h[ibuf];
        const float* __restrict__ Bp = (k0g < HD) ? Wl : Wr;
        int col0 = k0g & 127;
        __syncthreads();
        // stage A: 128 rows x 32 k  (1024 float4 tasks / 256 thr = 4 each)
#pragma unroll
        for (int it = 0; it < 4; it++) {
            int i = tid + it * 256;
            int row = i >> 3, kq = i & 7;
            int grow = brow + row;
            float4 v = make_float4(0.f, 0.f, 0.f, 0.f);
            if (grow < NN) v = *(const float4*)(Ap + grow * HD + col0 + kq * 4);
            float hx, lx, hy, ly, hz, lz, hw, lw;
            split2(v.x, hx, lx); split2(v.y, hy, ly);
            split2(v.z, hz, lz); split2(v.w, hw, lw);
            int o = row * KPW + kq * 2;
            As_hi[o]     = pack2(hx, hy);
            As_hi[o + 1] = pack2(hz, hw);
            As_lo[o]     = pack2(lx, ly);
            As_lo[o + 1] = pack2(lz, lw);
        }
        // stage B: 128 cols x 32 k from Wl/Wr [c][k]
#pragma unroll
        for (int it = 0; it < 4; it++) {
            int i = tid + it * 256;
            int c = i >> 3, kq = i & 7;
            float4 v = *(const float4*)(Bp + c * HD + col0 + kq * 4);
            float hx, lx, hy, ly, hz, lz, hw, lw;
            split2(v.x, hx, lx); split2(v.y, hy, ly);
            split2(v.z, hz, lz); split2(v.w, hw, lw);
            int o = c * KPW + kq * 2;
            Bs_hi[o]     = pack2(hx, hy);
            Bs_hi[o + 1] = pack2(hz, hw);
            Bs_lo[o]     = pack2(lx, ly);
            Bs_lo[o + 1] = pack2(lz, lw);
        }
        __syncthreads();

#pragma unroll
        for (int ks = 0; ks < 2; ks++) {
            int kw = ks * 8;   // word offset of this k16 sub-chunk
            uint32_t ah[2][4], al[2][4], bh[8][2], bl[8][2];
#pragma unroll
            for (int mi = 0; mi < 2; mi++) {
                int r0 = (wrow + mi * 16 + g) * KPW + kw;
                ah[mi][0] = As_hi[r0 + t];
                ah[mi][1] = As_hi[r0 + 8 * KPW + t];
                ah[mi][2] = As_hi[r0 + t + 4];
                ah[mi][3] = As_hi[r0 + 8 * KPW + t + 4];
                al[mi][0] = As_lo[r0 + t];
                al[mi][1] = As_lo[r0 + 8 * KPW + t];
                al[mi][2] = As_lo[r0 + t + 4];
                al[mi][3] = As_lo[r0 + 8 * KPW + t + 4];
            }
#pragma unroll
            for (int ni = 0; ni < 8; ni++) {
                int c0 = (wcol + ni * 8 + g) * KPW + kw;
                bh[ni][0] = Bs_hi[c0 + t];
                bh[ni][1] = Bs_hi[c0 + t + 4];
                bl[ni][0] = Bs_lo[c0 + t];
                bl[ni][1] = Bs_lo[c0 + t + 4];
            }
#pragma unroll
            for (int mi = 0; mi < 2; mi++)
#pragma unroll
                for (int ni = 0; ni < 8; ni++) {
                    mma_bf16(acc[mi][ni], ah[mi][0], ah[mi][1], ah[mi][2], ah[mi][3],
                             bh[ni][0], bh[ni][1]);
                    mma_bf16(acc[mi][ni], al[mi][0], al[mi][1], al[mi][2], al[mi][3],
                             bh[ni][0], bh[ni][1]);
                    mma_bf16(acc[mi][ni], ah[mi][0], ah[mi][1], ah[mi][2], ah[mi][3],
                             bl[ni][0], bl[ni][1]);
                }
        }
    }
    __syncthreads();

    // ---- epilogue: bias + LN(128 cols) + ReLU ----
    float ps[2][2], pq[2][2];
#pragma unroll
    for (int mi = 0; mi < 2; mi++)
#pragma unroll
        for (int h = 0; h < 2; h++) { ps[mi][h] = 0.f; pq[mi][h] = 0.f; }
#pragma unroll
    for (int mi = 0; mi < 2; mi++)
#pragma unroll
        for (int ni = 0; ni < 8; ni++) {
            int cbase = wcol + ni * 8 + 2 * t;
            float b0v = bias_s[cbase], b1v = bias_s[cbase + 1];
            float v;
            v = acc[mi][ni][0] + b0v; acc[mi][ni][0] = v; ps[mi][0] += v; pq[mi][0] += v * v;
            v = acc[mi][ni][1] + b1v; acc[mi][ni][1] = v; ps[mi][0] += v; pq[mi][0] += v * v;
            v = acc[mi][ni][2] + b0v; acc[mi][ni][2] = v; ps[mi][1] += v; pq[mi][1] += v * v;
            v = acc[mi][ni][3] + b1v; acc[mi][ni][3] = v; ps[mi][1] += v; pq[mi][1] += v * v;
        }
#pragma unroll
    for (int mi = 0; mi < 2; mi++)
#pragma unroll
        for (int h = 0; h < 2; h++) {
#pragma unroll
            for (int o = 1; o < 4; o <<= 1) {
                ps[mi][h] += __shfl_xor_sync(0xffffffffu, ps[mi][h], o);
                pq[mi][h] += __shfl_xor_sync(0xffffffffu, pq[mi][h], o);
            }
        }
    if (t == 0) {
#pragma unroll
        for (int mi = 0; mi < 2; mi++)
#pragma unroll
            for (int h = 0; h < 2; h++) {
                int rl = wrow + mi * 16 + h * 8 + g;
                red[rl * 4 + (warp & 1) * 2 + 0] = ps[mi][h];
                red[rl * 4 + (warp & 1) * 2 + 1] = pq[mi][h];
            }
    }
    __syncthreads();
#pragma unroll
    for (int mi = 0; mi < 2; mi++)
#pragma unroll
        for (int h = 0; h < 2; h++) {
            int rl = wrow + mi * 16 + h * 8 + g;
            float S = red[rl * 4 + 0] + red[rl * 4 + 2];
            float Q = red[rl * 4 + 1] + red[rl * 4 + 3];
            float mean = S * (1.f / HD);
            float var = Q * (1.f / HD) - mean * mean;
            float rstd = rsqrtf(var + EPS);
            int grow = brow + rl;
            if (grow < NN) {
#pragma unroll
                for (int ni = 0; ni < 8; ni++) {
                    int cbase = wcol + ni * 8 + 2 * t;
                    float v0 = acc[mi][ni][h * 2 + 0];
                    float v1 = acc[mi][ni][h * 2 + 1];
                    float o0 = fmaxf((v0 - mean) * rstd * gamma_s[cbase] + beta_s[cbase], 0.f);
                    float o1 = fmaxf((v1 - mean) * rstd * gamma_s[cbase + 1] + beta_s[cbase + 1], 0.f);
                    *(float2*)(out + grow * HD + cbase) = make_float2(o0, o1);
                }
            }
        }
}

// ---------------- pooling ----------------
__global__ void zero_pool(float* __restrict__ gout) {
    int i = blockIdx.x * blockDim.x + threadIdx.x;
    if (i < BG * 2 * HD) gout[i] = 0.f;
    if (i < BG) g_cnt[i] = 0.f;
}
__global__ void count_batch(const int* __restrict__ batch) {
    int i = blockIdx.x * blockDim.x + threadIdx.x;
    if (i < NN) atomicAdd(&g_cnt[batch[i]], 1.f);
}
__global__ void pool_accum(const float* __restrict__ ne, const int* __restrict__ batch,
                           float* __restrict__ gout) {
    int tx = threadIdx.x;  // 128 = column
    int n0 = blockIdx.x * 128;
    int n1 = min(n0 + 128, NN);
    if (n0 >= NN) return;
    int cur = batch[n0];
    float sum = 0.f, mx = 0.f;
    for (int n = n0; n < n1; n++) {
        int b = batch[n];
        float v = ne[n * HD + tx];
        if (b != cur) {
            atomicAdd(&gout[cur * 256 + tx], sum);
            atomicMax((int*)&gout[cur * 256 + HD + tx], __float_as_int(mx));
            sum = 0.f; mx = 0.f; cur = b;
        }
        sum += v;
        mx = fmaxf(mx, v);
    }
    atomicAdd(&gout[cur * 256 + tx], sum);
    atomicMax((int*)&gout[cur * 256 + HD + tx], __float_as_int(mx));
}
__global__ void finalize_pool(float* __restrict__ gout) {
    int b = blockIdx.x;
    int tx = threadIdx.x;
    gout[b * 256 + tx] /= fmaxf(g_cnt[b], 1.f);
}

// ---------------- launch ----------------
extern "C" void kernel_launch(void* const* d_in, const int* in_sizes, int n_in,
                              void* d_out, int out_size) {
    const float* x   = (const float*)d_in[0];
    const int* ei    = (const int*)d_in[1];
    const int* batch = (const int*)d_in[2];
    const float* W0  = (const float*)d_in[3];
    const float* b0  = (const float*)d_in[4];
    const float* g0  = (const float*)d_in[5];
    const float* be0 = (const float*)d_in[6];
    const float* Wl1 = (const float*)d_in[7];
    const float* bl1 = (const float*)d_in[8];
    const float* Wr1 = (const float*)d_in[9];
    const float* g1  = (const float*)d_in[10];
    const float* be1 = (const float*)d_in[11];
    const float* Wl2 = (const float*)d_in[12];
    const float* bl2 = (const float*)d_in[13];
    const float* Wr2 = (const float*)d_in[14];
    const float* g2  = (const float*)d_in[15];
    const float* be2 = (const float*)d_in[16];
    const float* Wl3 = (const float*)d_in[17];
    const float* bl3 = (const float*)d_in[18];
    const float* Wr3 = (const float*)d_in[19];
    const float* g3  = (const float*)d_in[20];
    const float* be3 = (const float*)d_in[21];

    float* out = (float*)d_out;
    float* ne = out;                           // node_embed (N*H)
    float* gr = out + (size_t)NN * HD;         // graph_embed (B*2H)

    const int* src = ei;
    const int* dst = ei + EE;

    embed_kernel<<<(NN + 15) / 16, 128>>>(x, W0, b0, g0, be0);

    init_deg<<<NB_SCAN, 256>>>();
    count_deg<<<(EE + 255) / 256, 256>>>(dst);
    scan1<<<NB_SCAN, 256>>>();
    scan2<<<1, 512>>>();
    scan3<<<NB_SCAN, 256>>>();
    fill_csr<<<(EE + 255) / 256, 256>>>(src, dst);

    int gemm_blocks = (NN + 127) / 128;
    int agg_blocks = (NN * 32 + 255) / 256;

    // layer 1: h0 -> h1
    aggregate<<<agg_blocks, 256>>>(0);
    gemm_fused_bf16<<<gemm_blocks, 256>>>(0, Wl1, Wr1, bl1, g1, be1, 1, nullptr);
    // layer 2: h1 -> h0
    aggregate<<<agg_blocks, 256>>>(1);
    gemm_fused_bf16<<<gemm_blocks, 256>>>(1, Wl2, Wr2, bl2, g2, be2, 0, nullptr);
    // layer 3: h0 -> d_out node region
    aggregate<<<agg_blocks, 256>>>(0);
    gemm_fused_bf16<<<gemm_blocks, 256>>>(0, Wl3, Wr3, bl3, g3, be3, 0, ne);

    zero_pool<<<(BG * 2 * HD + 255) / 256, 256>>>(gr);
    count_batch<<<NB_SCAN, 256>>>(batch);
    pool_accum<<<(NN + 127) / 128, 128>>>(ne, batch, gr);
    finalize_pool<<<BG, 128>>>(gr);
}

// round 7
// speedup vs baseline: 1.5625x; 1.2035x over previous
#include <cuda_runtime.h>
#include <cuda_fp16.h>
#include <cstdint>

#define NN 100000
#define EE 1600000
#define BG 64
#define HD 128
#define DIN 9
#define EPS 1e-5f
#define NB_SCAN 391   // ceil(NN/256)

// ---------------- scratch (static __device__, no allocation) ----------------
__device__ __half g_h[2][NN * HD];       // ping-pong node features (fp16)
__device__ float  g_agg[NN * HD];        // mean-aggregated features (fp32)
__device__ int    g_deg[NN];
__device__ int    g_rowptr[NN];
__device__ int    g_cursor[NN];
__device__ int    g_col[EE];
__device__ int    g_bsum[512];
__device__ int    g_boff[512];
__device__ float  g_cnt[BG];

// ---------------- fp16 helpers ----------------
__device__ __forceinline__ uint32_t pack2h(float a, float b) {
    __half2 t = __floats2half2_rn(a, b);  // .x = a (low 16 bits)
    return *(uint32_t*)&t;
}
__device__ __forceinline__ void split2h(float x, float& hi, float& lo) {
    hi = __half2float(__float2half_rn(x));
    lo = x - hi;
}
__device__ __forceinline__ void mma_f16(float* c, uint32_t a0, uint32_t a1,
                                        uint32_t a2, uint32_t a3,
                                        uint32_t b0, uint32_t b1) {
    asm volatile(
        "mma.sync.aligned.m16n8k16.row.col.f32.f16.f16.f32 "
        "{%0,%1,%2,%3},{%4,%5,%6,%7},{%8,%9},{%0,%1,%2,%3};\n"
        : "+f"(c[0]), "+f"(c[1]), "+f"(c[2]), "+f"(c[3])
        : "r"(a0), "r"(a1), "r"(a2), "r"(a3), "r"(b0), "r"(b1));
}

// ---------------- node embedder: h = ReLU(LN(x@W0^T + b0)) -> fp16 ----------------
__global__ void embed_kernel(const float* __restrict__ x, const float* __restrict__ W0,
                             const float* __restrict__ b0, const float* __restrict__ g0,
                             const float* __restrict__ be0) {
    __shared__ float Ws[HD * DIN];
    __shared__ float xs[DIN];
    __shared__ float redS[4], redQ[4];
    int tx = threadIdx.x;  // 128 threads
    for (int i = tx; i < HD * DIN; i += 128) Ws[i] = W0[i];
    float bb = b0[tx], gg = g0[tx], be = be0[tx];
    int node0 = blockIdx.x * 16;
    __half* hout = g_h[0];

    for (int nn = 0; nn < 16; nn++) {
        int n = node0 + nn;
        __syncthreads();
        if (n < NN && tx < DIN) xs[tx] = x[n * DIN + tx];
        __syncthreads();
        float v = bb;
        if (n < NN) {
#pragma unroll
            for (int j = 0; j < DIN; j++) v += xs[j] * Ws[tx * DIN + j];
        } else {
            v = 0.f;
        }
        float s = v, s2 = v * v;
#pragma unroll
        for (int o = 16; o; o >>= 1) {
            s += __shfl_xor_sync(0xffffffffu, s, o);
            s2 += __shfl_xor_sync(0xffffffffu, s2, o);
        }
        if ((tx & 31) == 0) { redS[tx >> 5] = s; redQ[tx >> 5] = s2; }
        __syncthreads();
        s  = redS[0] + redS[1] + redS[2] + redS[3];
        s2 = redQ[0] + redQ[1] + redQ[2] + redQ[3];
        float mean = s * (1.f / HD);
        float var = s2 * (1.f / HD) - mean * mean;
        float rstd = rsqrtf(var + EPS);
        if (n < NN) {
            float o = fmaxf((v - mean) * rstd * gg + be, 0.f);
            hout[n * HD + tx] = __float2half_rn(o);
        }
    }
}

// ---------------- CSR construction ----------------
__global__ void init_deg() {
    int i = blockIdx.x * blockDim.x + threadIdx.x;
    if (i < NN) g_deg[i] = 0;
}
__global__ void count_deg(const int* __restrict__ dst) {
    int e = blockIdx.x * blockDim.x + threadIdx.x;
    if (e < EE) atomicAdd(&g_deg[dst[e]], 1);
}
__global__ void scan1() {
    __shared__ int sm[256];
    int t = threadIdx.x;
    int i = blockIdx.x * 256 + t;
    sm[t] = (i < NN) ? g_deg[i] : 0;
    __syncthreads();
#pragma unroll
    for (int o = 128; o; o >>= 1) {
        if (t < o) sm[t] += sm[t + o];
        __syncthreads();
    }
    if (t == 0) g_bsum[blockIdx.x] = sm[0];
}
__global__ void scan2() {
    __shared__ int sm[512];
    int t = threadIdx.x;
    int v = (t < NB_SCAN) ? g_bsum[t] : 0;
    sm[t] = v;
    __syncthreads();
    for (int o = 1; o < 512; o <<= 1) {
        int add = (t >= o) ? sm[t - o] : 0;
        __syncthreads();
        sm[t] += add;
        __syncthreads();
    }
    if (t < NB_SCAN) g_boff[t] = sm[t] - v;  // exclusive
}
__global__ void scan3() {
    __shared__ int sm[256];
    int t = threadIdx.x;
    int i = blockIdx.x * 256 + t;
    int v = (i < NN) ? g_deg[i] : 0;
    sm[t] = v;
    __syncthreads();
    for (int o = 1; o < 256; o <<= 1) {
        int add = (t >= o) ? sm[t - o] : 0;
        __syncthreads();
        sm[t] += add;
        __syncthreads();
    }
    if (i < NN) {
        int excl = sm[t] - v + g_boff[blockIdx.x];
        g_rowptr[i] = excl;
        g_cursor[i] = excl;
    }
}
__global__ void fill_csr(const int* __restrict__ src, const int* __restrict__ dst) {
    int e = blockIdx.x * blockDim.x + threadIdx.x;
    if (e < EE) {
        int p = atomicAdd(&g_cursor[dst[e]], 1);
        g_col[p] = src[e];
    }
}

// ---------------- mean aggregation: warp per destination node (fp16 gather) ----------------
__global__ void __launch_bounds__(256) aggregate(int ibuf) {
    int warp = (blockIdx.x * blockDim.x + threadIdx.x) >> 5;
    int lane4 = (threadIdx.x & 31) * 4;   // 4 features per lane
    if (warp >= NN) return;
    const __half* __restrict__ h = g_h[ibuf];
    int start = g_rowptr[warp];
    int d = g_deg[warp];
    float4 acc = make_float4(0.f, 0.f, 0.f, 0.f);
    int j = 0;
    for (; j + 3 < d; j += 4) {
        int s0 = g_col[start + j];
        int s1 = g_col[start + j + 1];
        int s2 = g_col[start + j + 2];
        int s3 = g_col[start + j + 3];
        uint2 r0 = *(const uint2*)(h + s0 * HD + lane4);
        uint2 r1 = *(const uint2*)(h + s1 * HD + lane4);
        uint2 r2 = *(const uint2*)(h + s2 * HD + lane4);
        uint2 r3 = *(const uint2*)(h + s3 * HD + lane4);
#pragma unroll
        for (int q = 0; q < 4; q++) {
            uint2 r = (q == 0) ? r0 : (q == 1) ? r1 : (q == 2) ? r2 : r3;
            float2 a = __half22float2(*(__half2*)&r.x);
            float2 b = __half22float2(*(__half2*)&r.y);
            acc.x += a.x; acc.y += a.y; acc.z += b.x; acc.w += b.y;
        }
    }
    for (; j < d; j++) {
        int s = g_col[start + j];
        uint2 r = *(const uint2*)(h + s * HD + lane4);
        float2 a = __half22float2(*(__half2*)&r.x);
        float2 b = __half22float2(*(__half2*)&r.y);
        acc.x += a.x; acc.y += a.y; acc.z += b.x; acc.w += b.y;
    }
    float inv = 1.f / (float)max(d, 1);
    acc.x *= inv; acc.y *= inv; acc.z *= inv; acc.w *= inv;
    *(float4*)(g_agg + warp * HD + lane4) = acc;
}

// ---------------- fp16 split tensor-core GEMM + bias + LayerNorm + ReLU ----------------
// Block: 128 rows x 128 cols. 8 warps as 4x2, warptile 32x64.
// K = 256 logical:
//   kc 0..3 (k<128):  A = g_agg (fp32, 3-term split), B = Wl (split)
//   kc 4..7 (k>=128): A = g_h (fp16 EXACT, 2 terms),  B = Wr (split)
// smem padded stride 20 words -> conflict-free frag LDS.
#define KPW 20   // uint32 words per row per 32-k chunk

__global__ void __launch_bounds__(256) gemm_fused_f16(
    int ibuf,
    const float* __restrict__ Wl, const float* __restrict__ Wr,
    const float* __restrict__ bias, const float* __restrict__ gamma,
    const float* __restrict__ beta,
    int obuf, float* __restrict__ ext_out) {
    __shared__ uint32_t As_hi[128 * KPW], As_lo[128 * KPW];
    __shared__ uint32_t Bs_hi[128 * KPW], Bs_lo[128 * KPW];
    __shared__ float bias_s[128], gamma_s[128], beta_s[128];
    __shared__ float red[128 * 4];

    __half* __restrict__ out_h = g_h[obuf];

    int tid = threadIdx.x;
    int lane = tid & 31;
    int warp = tid >> 5;
    int g = lane >> 2;
    int t = lane & 3;
    int wrow = (warp >> 1) * 32;   // 4 warp-rows of 32
    int wcol = (warp & 1) * 64;    // 2 warp-cols of 64
    int brow = blockIdx.x * 128;

    if (tid < 128) {
        bias_s[tid] = bias[tid];
        gamma_s[tid] = gamma[tid];
        beta_s[tid] = beta[tid];
    }

    float acc[2][8][4];
#pragma unroll
    for (int mi = 0; mi < 2; mi++)
#pragma unroll
        for (int ni = 0; ni < 8; ni++)
#pragma unroll
            for (int c = 0; c < 4; c++) acc[mi][ni][c] = 0.f;

    for (int kc = 0; kc < 8; kc++) {
        const bool isagg = (kc < 4);
        int col0 = (kc * 32) & 127;
        __syncthreads();
        // ---- stage A: 128 rows x 32 k ----
        if (isagg) {
#pragma unroll
            for (int it = 0; it < 4; it++) {
                int i = tid + it * 256;
                int row = i >> 3, kq = i & 7;
                int grow = brow + row;
                float4 v = make_float4(0.f, 0.f, 0.f, 0.f);
                if (grow < NN) v = *(const float4*)(g_agg + grow * HD + col0 + kq * 4);
                float hx, lx, hy, ly, hz, lz, hw, lw;
                split2h(v.x, hx, lx); split2h(v.y, hy, ly);
                split2h(v.z, hz, lz); split2h(v.w, hw, lw);
                int o = row * KPW + kq * 2;
                As_hi[o]     = pack2h(hx, hy);
                As_hi[o + 1] = pack2h(hz, hw);
                As_lo[o]     = pack2h(lx, ly);
                As_lo[o + 1] = pack2h(lz, lw);
            }
        } else {
            const __half* __restrict__ Hp = g_h[ibuf];
#pragma unroll
            for (int it = 0; it < 4; it++) {
                int i = tid + it * 256;
                int row = i >> 3, kq = i & 7;
                int grow = brow + row;
                uint2 v = make_uint2(0u, 0u);
                if (grow < NN) v = *(const uint2*)(Hp + grow * HD + col0 + kq * 4);
                int o = row * KPW + kq * 2;
                As_hi[o]     = v.x;   // already packed fp16 pairs, exact
                As_hi[o + 1] = v.y;
            }
        }
        // ---- stage B: 128 cols x 32 k from Wl/Wr [c][k] ----
        {
            const float* __restrict__ Bp = isagg ? Wl : Wr;
#pragma unroll
            for (int it = 0; it < 4; it++) {
                int i = tid + it * 256;
                int c = i >> 3, kq = i & 7;
                float4 v = *(const float4*)(Bp + c * HD + col0 + kq * 4);
                float hx, lx, hy, ly, hz, lz, hw, lw;
                split2h(v.x, hx, lx); split2h(v.y, hy, ly);
                split2h(v.z, hz, lz); split2h(v.w, hw, lw);
                int o = c * KPW + kq * 2;
                Bs_hi[o]     = pack2h(hx, hy);
                Bs_hi[o + 1] = pack2h(hz, hw);
                Bs_lo[o]     = pack2h(lx, ly);
                Bs_lo[o + 1] = pack2h(lz, lw);
            }
        }
        __syncthreads();

#pragma unroll
        for (int ks = 0; ks < 2; ks++) {
            int kw = ks * 8;   // word offset of this k16 sub-chunk
            uint32_t ah[2][4], al[2][4], bh[8][2], bl[8][2];
#pragma unroll
            for (int mi = 0; mi < 2; mi++) {
                int r0 = (wrow + mi * 16 + g) * KPW + kw;
                ah[mi][0] = As_hi[r0 + t];
                ah[mi][1] = As_hi[r0 + 8 * KPW + t];
                ah[mi][2] = As_hi[r0 + t + 4];
                ah[mi][3] = As_hi[r0 + 8 * KPW + t + 4];
                if (isagg) {
                    al[mi][0] = As_lo[r0 + t];
                    al[mi][1] = As_lo[r0 + 8 * KPW + t];
                    al[mi][2] = As_lo[r0 + t + 4];
                    al[mi][3] = As_lo[r0 + 8 * KPW + t + 4];
                }
            }
#pragma unroll
            for (int ni = 0; ni < 8; ni++) {
                int c0 = (wcol + ni * 8 + g) * KPW + kw;
                bh[ni][0] = Bs_hi[c0 + t];
                bh[ni][1] = Bs_hi[c0 + t + 4];
                bl[ni][0] = Bs_lo[c0 + t];
                bl[ni][1] = Bs_lo[c0 + t + 4];
            }
#pragma unroll
            for (int mi = 0; mi < 2; mi++)
#pragma unroll
                for (int ni = 0; ni < 8; ni++) {
                    mma_f16(acc[mi][ni], ah[mi][0], ah[mi][1], ah[mi][2], ah[mi][3],
                            bh[ni][0], bh[ni][1]);
                    if (isagg)
                        mma_f16(acc[mi][ni], al[mi][0], al[mi][1], al[mi][2], al[mi][3],
                                bh[ni][0], bh[ni][1]);
                    mma_f16(acc[mi][ni], ah[mi][0], ah[mi][1], ah[mi][2], ah[mi][3],
                            bl[ni][0], bl[ni][1]);
                }
        }
    }
    __syncthreads();

    // ---- epilogue: bias + LN(128 cols) + ReLU ----
    float ps[2][2], pq[2][2];
#pragma unroll
    for (int mi = 0; mi < 2; mi++)
#pragma unroll
        for (int h = 0; h < 2; h++) { ps[mi][h] = 0.f; pq[mi][h] = 0.f; }
#pragma unroll
    for (int mi = 0; mi < 2; mi++)
#pragma unroll
        for (int ni = 0; ni < 8; ni++) {
            int cbase = wcol + ni * 8 + 2 * t;
            float b0v = bias_s[cbase], b1v = bias_s[cbase + 1];
            float v;
            v = acc[mi][ni][0] + b0v; acc[mi][ni][0] = v; ps[mi][0] += v; pq[mi][0] += v * v;
            v = acc[mi][ni][1] + b1v; acc[mi][ni][1] = v; ps[mi][0] += v; pq[mi][0] += v * v;
            v = acc[mi][ni][2] + b0v; acc[mi][ni][2] = v; ps[mi][1] += v; pq[mi][1] += v * v;
            v = acc[mi][ni][3] + b1v; acc[mi][ni][3] = v; ps[mi][1] += v; pq[mi][1] += v * v;
        }
#pragma unroll
    for (int mi = 0; mi < 2; mi++)
#pragma unroll
        for (int h = 0; h < 2; h++) {
#pragma unroll
            for (int o = 1; o < 4; o <<= 1) {
                ps[mi][h] += __shfl_xor_sync(0xffffffffu, ps[mi][h], o);
                pq[mi][h] += __shfl_xor_sync(0xffffffffu, pq[mi][h], o);
            }
        }
    if (t == 0) {
#pragma unroll
        for (int mi = 0; mi < 2; mi++)
#pragma unroll
            for (int h = 0; h < 2; h++) {
                int rl = wrow + mi * 16 + h * 8 + g;
                red[rl * 4 + (warp & 1) * 2 + 0] = ps[mi][h];
                red[rl * 4 + (warp & 1) * 2 + 1] = pq[mi][h];
            }
    }
    __syncthreads();
#pragma unroll
    for (int mi = 0; mi < 2; mi++)
#pragma unroll
        for (int h = 0; h < 2; h++) {
            int rl = wrow + mi * 16 + h * 8 + g;
            float S = red[rl * 4 + 0] + red[rl * 4 + 2];
            float Q = red[rl * 4 + 1] + red[rl * 4 + 3];
            float mean = S * (1.f / HD);
            float var = Q * (1.f / HD) - mean * mean;
            float rstd = rsqrtf(var + EPS);
            int grow = brow + rl;
            if (grow < NN) {
#pragma unroll
                for (int ni = 0; ni < 8; ni++) {
                    int cbase = wcol + ni * 8 + 2 * t;
                    float v0 = acc[mi][ni][h * 2 + 0];
                    float v1 = acc[mi][ni][h * 2 + 1];
                    float o0 = fmaxf((v0 - mean) * rstd * gamma_s[cbase] + beta_s[cbase], 0.f);
                    float o1 = fmaxf((v1 - mean) * rstd * gamma_s[cbase + 1] + beta_s[cbase + 1], 0.f);
                    if (ext_out) {
                        *(float2*)(ext_out + grow * HD + cbase) = make_float2(o0, o1);
                    } else {
                        *(uint32_t*)(out_h + grow * HD + cbase) = pack2h(o0, o1);
                    }
                }
            }
        }
}

// ---------------- pooling ----------------
__global__ void zero_pool(float* __restrict__ gout) {
    int i = blockIdx.x * blockDim.x + threadIdx.x;
    if (i < BG * 2 * HD) gout[i] = 0.f;
    if (i < BG) g_cnt[i] = 0.f;
}
__global__ void count_batch(const int* __restrict__ batch) {
    int i = blockIdx.x * blockDim.x + threadIdx.x;
    if (i < NN) atomicAdd(&g_cnt[batch[i]], 1.f);
}
__global__ void pool_accum(const float* __restrict__ ne, const int* __restrict__ batch,
                           float* __restrict__ gout) {
    int tx = threadIdx.x;  // 128 = column
    int n0 = blockIdx.x * 128;
    int n1 = min(n0 + 128, NN);
    if (n0 >= NN) return;
    int cur = batch[n0];
    float sum = 0.f, mx = 0.f;
    for (int n = n0; n < n1; n++) {
        int b = batch[n];
        float v = ne[n * HD + tx];
        if (b != cur) {
            atomicAdd(&gout[cur * 256 + tx], sum);
            atomicMax((int*)&gout[cur * 256 + HD + tx], __float_as_int(mx));
            sum = 0.f; mx = 0.f; cur = b;
        }
        sum += v;
        mx = fmaxf(mx, v);
    }
    atomicAdd(&gout[cur * 256 + tx], sum);
    atomicMax((int*)&gout[cur * 256 + HD + tx], __float_as_int(mx));
}
__global__ void finalize_pool(float* __restrict__ gout) {
    int b = blockIdx.x;
    int tx = threadIdx.x;
    gout[b * 256 + tx] /= fmaxf(g_cnt[b], 1.f);
}

// ---------------- launch ----------------
extern "C" void kernel_launch(void* const* d_in, const int* in_sizes, int n_in,
                              void* d_out, int out_size) {
    const float* x   = (const float*)d_in[0];
    const int* ei    = (const int*)d_in[1];
    const int* batch = (const int*)d_in[2];
    const float* W0  = (const float*)d_in[3];
    const float* b0  = (const float*)d_in[4];
    const float* g0  = (const float*)d_in[5];
    const float* be0 = (const float*)d_in[6];
    const float* Wl1 = (const float*)d_in[7];
    const float* bl1 = (const float*)d_in[8];
    const float* Wr1 = (const float*)d_in[9];
    const float* g1  = (const float*)d_in[10];
    const float* be1 = (const float*)d_in[11];
    const float* Wl2 = (const float*)d_in[12];
    const float* bl2 = (const float*)d_in[13];
    const float* Wr2 = (const float*)d_in[14];
    const float* g2  = (const float*)d_in[15];
    const float* be2 = (const float*)d_in[16];
    const float* Wl3 = (const float*)d_in[17];
    const float* bl3 = (const float*)d_in[18];
    const float* Wr3 = (const float*)d_in[19];
    const float* g3  = (const float*)d_in[20];
    const float* be3 = (const float*)d_in[21];

    float* out = (float*)d_out;
    float* ne = out;                           // node_embed (N*H)
    float* gr = out + (size_t)NN * HD;         // graph_embed (B*2H)

    const int* src = ei;
    const int* dst = ei + EE;

    embed_kernel<<<(NN + 15) / 16, 128>>>(x, W0, b0, g0, be0);

    init_deg<<<NB_SCAN, 256>>>();
    count_deg<<<(EE + 255) / 256, 256>>>(dst);
    scan1<<<NB_SCAN, 256>>>();
    scan2<<<1, 512>>>();
    scan3<<<NB_SCAN, 256>>>();
    fill_csr<<<(EE + 255) / 256, 256>>>(src, dst);

    int gemm_blocks = (NN + 127) / 128;
    int agg_blocks = (NN * 32 + 255) / 256;

    // layer 1: h0 -> h1
    aggregate<<<agg_blocks, 256>>>(0);
    gemm_fused_f16<<<gemm_blocks, 256>>>(0, Wl1, Wr1, bl1, g1, be1, 1, nullptr);
    // layer 2: h1 -> h0
    aggregate<<<agg_blocks, 256>>>(1);
    gemm_fused_f16<<<gemm_blocks, 256>>>(1, Wl2, Wr2, bl2, g2, be2, 0, nullptr);
    // layer 3: h0 -> d_out node region (fp32)
    aggregate<<<agg_blocks, 256>>>(0);
    gemm_fused_f16<<<gemm_blocks, 256>>>(0, Wl3, Wr3, bl3, g3, be3, 0, ne);

    zero_pool<<<(BG * 2 * HD + 255) / 256, 256>>>(gr);
    count_batch<<<NB_SCAN, 256>>>(batch);
    pool_accum<<<(NN + 127) / 128, 128>>>(ne, batch, gr);
    finalize_pool<<<BG, 128>>>(gr);
}

// round 9
// speedup vs baseline: 1.6514x; 1.0569x over previous
#include <cuda_runtime.h>
#include <cuda_fp16.h>
#include <cstdint>

#define NN 100000
#define EE 1600000
#define BG 64
#define HD 128
#define DIN 9
#define EPS 1e-5f
#define NB_SCAN 391      // ceil(NN/256)
#define EMB_BLOCKS 3125  // 32 nodes per block
#define CD_BLOCKS 6250   // count_deg blocks

// ---------------- scratch (static __device__, no allocation) ----------------
__device__ __half g_h[2][NN * HD];       // ping-pong node features (fp16)
__device__ float  g_agg[NN * HD];        // mean-aggregated features (fp32)
__device__ int    g_deg[NN];
__device__ int    g_rowptr[NN];
__device__ int    g_cursor[NN];
__device__ int    g_col[EE];
__device__ int    g_bsum[512];
__device__ int    g_boff[512];
__device__ float  g_cnt[BG];

// ---------------- fp16 helpers ----------------
__device__ __forceinline__ uint32_t pack2h(float a, float b) {
    __half2 t = __floats2half2_rn(a, b);
    return *(uint32_t*)&t;
}
__device__ __forceinline__ void split2h(float x, float& hi, float& lo) {
    hi = __half2float(__float2half_rn(x));
    lo = x - hi;
}
__device__ __forceinline__ void mma_f16(float* c, uint32_t a0, uint32_t a1,
                                        uint32_t a2, uint32_t a3,
                                        uint32_t b0, uint32_t b1) {
    asm volatile(
        "mma.sync.aligned.m16n8k16.row.col.f32.f16.f16.f32 "
        "{%0,%1,%2,%3},{%4,%5,%6,%7},{%8,%9},{%0,%1,%2,%3};\n"
        : "+f"(c[0]), "+f"(c[1]), "+f"(c[2]), "+f"(c[3])
        : "r"(a0), "r"(a1), "r"(a2), "r"(a3), "r"(b0), "r"(b1));
}

// ---------------- init zeroing (deg, cnt, graph-pool out) ----------------
__global__ void zero_misc(float* __restrict__ gr) {
    int i = blockIdx.x * blockDim.x + threadIdx.x;
    if (i < NN) g_deg[i] = 0;
    if (i < BG * 2 * HD) gr[i] = 0.f;
    if (i < BG) g_cnt[i] = 0.f;
}

// ---------------- fat start: embed || count_deg || count_batch ----------------
// embed: warp per node, lane l owns features 4l..4l+3, no __syncthreads in loop.
__global__ void __launch_bounds__(256) fat_start(
    const float* __restrict__ x, const float* __restrict__ W0,
    const float* __restrict__ b0, const float* __restrict__ g0,
    const float* __restrict__ be0,
    const int* __restrict__ dst, const int* __restrict__ batch) {
    int bid = blockIdx.x;
    int tid = threadIdx.x;
    if (bid < EMB_BLOCKS) {
        __shared__ float Ws[HD * DIN];
        __shared__ float bs[HD], gs[HD], es[HD];
        for (int i = tid; i < HD * DIN; i += 256) Ws[i] = W0[i];
        if (tid < HD) { bs[tid] = b0[tid]; gs[tid] = g0[tid]; es[tid] = be0[tid]; }
        __syncthreads();
        int warp = tid >> 5;
        int lane = tid & 31;
        __half* hout = g_h[0];
#pragma unroll
        for (int it = 0; it < 4; it++) {
            int n = bid * 32 + it * 8 + warp;   // always < NN (3125*32 == NN)
            float xv = (lane < DIN) ? x[n * DIN + lane] : 0.f;
            float xj[DIN];
#pragma unroll
            for (int j = 0; j < DIN; j++) xj[j] = __shfl_sync(0xffffffffu, xv, j);
            float val[4];
#pragma unroll
            for (int q = 0; q < 4; q++) {
                int f = lane * 4 + q;
                float v = bs[f];
#pragma unroll
                for (int j = 0; j < DIN; j++) v += xj[j] * Ws[f * DIN + j];
                val[q] = v;
            }
            float s = val[0] + val[1] + val[2] + val[3];
            float s2 = val[0]*val[0] + val[1]*val[1] + val[2]*val[2] + val[3]*val[3];
#pragma unroll
            for (int o = 16; o; o >>= 1) {
                s += __shfl_xor_sync(0xffffffffu, s, o);
                s2 += __shfl_xor_sync(0xffffffffu, s2, o);
            }
            float mean = s * (1.f / HD);
            float var = s2 * (1.f / HD) - mean * mean;
            float rstd = rsqrtf(var + EPS);
            uint2 w;
            {
                int f = lane * 4;
                float o0 = fmaxf((val[0] - mean) * rstd * gs[f] + es[f], 0.f);
                float o1 = fmaxf((val[1] - mean) * rstd * gs[f+1] + es[f+1], 0.f);
                float o2 = fmaxf((val[2] - mean) * rstd * gs[f+2] + es[f+2], 0.f);
                float o3 = fmaxf((val[3] - mean) * rstd * gs[f+3] + es[f+3], 0.f);
                w.x = pack2h(o0, o1);
                w.y = pack2h(o2, o3);
            }
            *(uint2*)(hout + n * HD + lane * 4) = w;
        }
    } else if (bid < EMB_BLOCKS + CD_BLOCKS) {
        int e = (bid - EMB_BLOCKS) * 256 + tid;
        if (e < EE) atomicAdd(&g_deg[dst[e]], 1);
    } else {
        int i = (bid - EMB_BLOCKS - CD_BLOCKS) * 256 + tid;
        if (i < NN) atomicAdd(&g_cnt[batch[i]], 1.f);
    }
}

// ---------------- CSR scans + fill ----------------
__global__ void scan1() {
    __shared__ int sm[256];
    int t = threadIdx.x;
    int i = blockIdx.x * 256 + t;
    sm[t] = (i < NN) ? g_deg[i] : 0;
    __syncthreads();
#pragma unroll
    for (int o = 128; o; o >>= 1) {
        if (t < o) sm[t] += sm[t + o];
        __syncthreads();
    }
    if (t == 0) g_bsum[blockIdx.x] = sm[0];
}
__global__ void scan2() {
    __shared__ int sm[512];
    int t = threadIdx.x;
    int v = (t < NB_SCAN) ? g_bsum[t] : 0;
    sm[t] = v;
    __syncthreads();
    for (int o = 1; o < 512; o <<= 1) {
        int add = (t >= o) ? sm[t - o] : 0;
        __syncthreads();
        sm[t] += add;
        __syncthreads();
    }
    if (t < NB_SCAN) g_boff[t] = sm[t] - v;  // exclusive
}
__global__ void scan3() {
    __shared__ int sm[256];
    int t = threadIdx.x;
    int i = blockIdx.x * 256 + t;
    int v = (i < NN) ? g_deg[i] : 0;
    sm[t] = v;
    __syncthreads();
    for (int o = 1; o < 256; o <<= 1) {
        int add = (t >= o) ? sm[t - o] : 0;
        __syncthreads();
        sm[t] += add;
        __syncthreads();
    }
    if (i < NN) {
        int excl = sm[t] - v + g_boff[blockIdx.x];
        g_rowptr[i] = excl;
        g_cursor[i] = excl;
    }
}
__global__ void fill_csr(const int* __restrict__ src, const int* __restrict__ dst) {
    int e = blockIdx.x * blockDim.x + threadIdx.x;
    if (e < EE) {
        int p = atomicAdd(&g_cursor[dst[e]], 1);
        g_col[p] = src[e];
    }
}

// ---------------- mean aggregation: 2 nodes per warp, uint4 gathers ----------------
__device__ __forceinline__ void acc8(float* acc, uint4 v) {
    float2 t;
    t = __half22float2(*(__half2*)&v.x); acc[0] += t.x; acc[1] += t.y;
    t = __half22float2(*(__half2*)&v.y); acc[2] += t.x; acc[3] += t.y;
    t = __half22float2(*(__half2*)&v.z); acc[4] += t.x; acc[5] += t.y;
    t = __half22float2(*(__half2*)&v.w); acc[6] += t.x; acc[7] += t.y;
}
__global__ void __launch_bounds__(256) aggregate(int ibuf) {
    int gwarp = (blockIdx.x * 256 + threadIdx.x) >> 5;
    int lane = threadIdx.x & 31;
    int node = gwarp * 2 + (lane >> 4);
    int l16 = lane & 15;
    if (node >= NN) return;
    const __half* __restrict__ h = g_h[ibuf];
    int start = g_rowptr[node];
    int d = g_deg[node];
    float acc[8] = {0.f, 0.f, 0.f, 0.f, 0.f, 0.f, 0.f, 0.f};
    int j = 0;
    for (; j + 3 < d; j += 4) {
        int s0 = g_col[start + j];
        int s1 = g_col[start + j + 1];
        int s2 = g_col[start + j + 2];
        int s3 = g_col[start + j + 3];
        uint4 v0 = *(const uint4*)(h + s0 * HD + l16 * 8);
        uint4 v1 = *(const uint4*)(h + s1 * HD + l16 * 8);
        uint4 v2 = *(const uint4*)(h + s2 * HD + l16 * 8);
        uint4 v3 = *(const uint4*)(h + s3 * HD + l16 * 8);
        acc8(acc, v0); acc8(acc, v1); acc8(acc, v2); acc8(acc, v3);
    }
    for (; j < d; j++) {
        int s = g_col[start + j];
        uint4 v = *(const uint4*)(h + s * HD + l16 * 8);
        acc8(acc, v);
    }
    float inv = 1.f / (float)max(d, 1);
#pragma unroll
    for (int q = 0; q < 8; q++) acc[q] *= inv;
    *(float4*)(g_agg + node * HD + l16 * 8)     = make_float4(acc[0], acc[1], acc[2], acc[3]);
    *(float4*)(g_agg + node * HD + l16 * 8 + 4) = make_float4(acc[4], acc[5], acc[6], acc[7]);
}

// ---------------- fp16 split tensor-core GEMM + bias + LayerNorm + ReLU ----------------
// Block 128x128, 8 warps as 4x2 (warptile 32x64). K=256 logical:
//   kc 0..3: A = g_agg (fp32, split -> 3 mma terms), B = Wl (split)
//   kc 4..7: A = g_h (fp16 exact -> 2 terms),        B = Wr (split)
// Software pipeline: prefetch chunk kc+1 global->regs during mma of chunk kc.
#define KPW 20   // uint32 words per row per 32-k chunk (padded)

__global__ void __launch_bounds__(256) gemm_fused_f16(
    int ibuf,
    const float* __restrict__ Wl, const float* __restrict__ Wr,
    const float* __restrict__ bias, const float* __restrict__ gamma,
    const float* __restrict__ beta,
    int obuf, float* __restrict__ ext_out) {
    __shared__ uint32_t As_hi[128 * KPW], As_lo[128 * KPW];
    __shared__ uint32_t Bs_hi[128 * KPW], Bs_lo[128 * KPW];
    __shared__ float bias_s[128], gamma_s[128], beta_s[128];
    __shared__ float red[128 * 4];

    __half* __restrict__ out_h = g_h[obuf];
    const __half* __restrict__ Hp = g_h[ibuf];

    int tid = threadIdx.x;
    int lane = tid & 31;
    int warp = tid >> 5;
    int g = lane >> 2;
    int t = lane & 3;
    int wrow = (warp >> 1) * 32;
    int wcol = (warp & 1) * 64;
    int brow = blockIdx.x * 128;

    if (tid < 128) {
        bias_s[tid] = bias[tid];
        gamma_s[tid] = gamma[tid];
        beta_s[tid] = beta[tid];
    }

    // per-thread staging coords
    int arow = tid >> 3, akq = tid & 7;      // base (it adds 32 rows / 32 cols)
    int agrow = brow + arow;

    float acc[2][8][4];
#pragma unroll
    for (int mi = 0; mi < 2; mi++)
#pragma unroll
        for (int ni = 0; ni < 8; ni++)
#pragma unroll
            for (int c = 0; c < 4; c++) acc[mi][ni][c] = 0.f;

    float4 pa[4];   // prefetched A (agg half, fp32)
    uint2  pah[4];  // prefetched A (h half, fp16)
    float4 pb[4];   // prefetched B (weights)

    // ---- prefetch chunk 0 ----
    {
        const int col0 = 0;
#pragma unroll
        for (int it = 0; it < 4; it++) {
            int grow = agrow + it * 32;
            pa[it] = (grow < NN) ? *(const float4*)(g_agg + grow * HD + col0 + akq * 4)
                                 : make_float4(0.f, 0.f, 0.f, 0.f);
            pb[it] = *(const float4*)(Wl + (arow + it * 32) * HD + col0 + akq * 4);
        }
    }

    for (int kc = 0; kc < 8; kc++) {
        const bool isagg = (kc < 4);
        __syncthreads();   // previous chunk's mma done reading smem
        // ---- store prefetched regs -> smem (with fp16 split) ----
        if (isagg) {
#pragma unroll
            for (int it = 0; it < 4; it++) {
                float4 v = pa[it];
                float hx, lx, hy, ly, hz, lz, hw, lw;
                split2h(v.x, hx, lx); split2h(v.y, hy, ly);
                split2h(v.z, hz, lz); split2h(v.w, hw, lw);
                int o = (arow + it * 32) * KPW + akq * 2;
                As_hi[o]     = pack2h(hx, hy);
                As_hi[o + 1] = pack2h(hz, hw);
                As_lo[o]     = pack2h(lx, ly);
                As_lo[o + 1] = pack2h(lz, lw);
            }
        } else {
#pragma unroll
            for (int it = 0; it < 4; it++) {
                int o = (arow + it * 32) * KPW + akq * 2;
                As_hi[o]     = pah[it].x;
                As_hi[o + 1] = pah[it].y;
            }
        }
#pragma unroll
        for (int it = 0; it < 4; it++) {
            float4 v = pb[it];
            float hx, lx, hy, ly, hz, lz, hw, lw;
            split2h(v.x, hx, lx); split2h(v.y, hy, ly);
            split2h(v.z, hz, lz); split2h(v.w, hw, lw);
            int o = (arow + it * 32) * KPW + akq * 2;
            Bs_hi[o]     = pack2h(hx, hy);
            Bs_hi[o + 1] = pack2h(hz, hw);
            Bs_lo[o]     = pack2h(lx, ly);
            Bs_lo[o + 1] = pack2h(lz, lw);
        }
        __syncthreads();
        // ---- prefetch next chunk (LDGs overlap the mma below) ----
        if (kc < 7) {
            int kn = kc + 1;
            bool nagg = (kn < 4);
            int col0 = (kn * 32) & 127;
            if (nagg) {
#pragma unroll
                for (int it = 0; it < 4; it++) {
                    int grow = agrow + it * 32;
                    pa[it] = (grow < NN)
                                 ? *(const float4*)(g_agg + grow * HD + col0 + akq * 4)
                                 : make_float4(0.f, 0.f, 0.f, 0.f);
                }
            } else {
#pragma unroll
                for (int it = 0; it < 4; it++) {
                    int grow = agrow + it * 32;
                    pah[it] = (grow < NN)
                                  ? *(const uint2*)(Hp + grow * HD + col0 + akq * 4)
                                  : make_uint2(0u, 0u);
                }
            }
            const float* __restrict__ Bp = nagg ? Wl : Wr;
#pragma unroll
            for (int it = 0; it < 4; it++)
                pb[it] = *(const float4*)(Bp + (arow + it * 32) * HD + col0 + akq * 4);
        }
        // ---- mma on chunk kc ----
#pragma unroll
        for (int ks = 0; ks < 2; ks++) {
            int kw = ks * 8;
            uint32_t ah[2][4], al[2][4], bh[8][2], bl[8][2];
#pragma unroll
            for (int mi = 0; mi < 2; mi++) {
                int r0 = (wrow + mi * 16 + g) * KPW + kw;
                ah[mi][0] = As_hi[r0 + t];
                ah[mi][1] = As_hi[r0 + 8 * KPW + t];
                ah[mi][2] = As_hi[r0 + t + 4];
                ah[mi][3] = As_hi[r0 + 8 * KPW + t + 4];
                if (isagg) {
                    al[mi][0] = As_lo[r0 + t];
                    al[mi][1] = As_lo[r0 + 8 * KPW + t];
                    al[mi][2] = As_lo[r0 + t + 4];
                    al[mi][3] = As_lo[r0 + 8 * KPW + t + 4];
                }
            }
#pragma unroll
            for (int ni = 0; ni < 8; ni++) {
                int c0 = (wcol + ni * 8 + g) * KPW + kw;
                bh[ni][0] = Bs_hi[c0 + t];
                bh[ni][1] = Bs_hi[c0 + t + 4];
                bl[ni][0] = Bs_lo[c0 + t];
                bl[ni][1] = Bs_lo[c0 + t + 4];
            }
#pragma unroll
            for (int mi = 0; mi < 2; mi++)
#pragma unroll
                for (int ni = 0; ni < 8; ni++) {
                    mma_f16(acc[mi][ni], ah[mi][0], ah[mi][1], ah[mi][2], ah[mi][3],
                            bh[ni][0], bh[ni][1]);
                    if (isagg)
                        mma_f16(acc[mi][ni], al[mi][0], al[mi][1], al[mi][2], al[mi][3],
                                bh[ni][0], bh[ni][1]);
                    mma_f16(acc[mi][ni], ah[mi][0], ah[mi][1], ah[mi][2], ah[mi][3],
                            bl[ni][0], bl[ni][1]);
                }
        }
    }
    __syncthreads();

    // ---- epilogue: bias + LN(128 cols) + ReLU ----
    float ps[2][2], pq[2][2];
#pragma unroll
    for (int mi = 0; mi < 2; mi++)
#pragma unroll
        for (int h = 0; h < 2; h++) { ps[mi][h] = 0.f; pq[mi][h] = 0.f; }
#pragma unroll
    for (int mi = 0; mi < 2; mi++)
#pragma unroll
        for (int ni = 0; ni < 8; ni++) {
            int cbase = wcol + ni * 8 + 2 * t;
            float b0v = bias_s[cbase], b1v = bias_s[cbase + 1];
            float v;
            v = acc[mi][ni][0] + b0v; acc[mi][ni][0] = v; ps[mi][0] += v; pq[mi][0] += v * v;
            v = acc[mi][ni][1] + b1v; acc[mi][ni][1] = v; ps[mi][0] += v; pq[mi][0] += v * v;
            v = acc[mi][ni][2] + b0v; acc[mi][ni][2] = v; ps[mi][1] += v; pq[mi][1] += v * v;
            v = acc[mi][ni][3] + b1v; acc[mi][ni][3] = v; ps[mi][1] += v; pq[mi][1] += v * v;
        }
#pragma unroll
    for (int mi = 0; mi < 2; mi++)
#pragma unroll
        for (int h = 0; h < 2; h++) {
#pragma unroll
            for (int o = 1; o < 4; o <<= 1) {
                ps[mi][h] += __shfl_xor_sync(0xffffffffu, ps[mi][h], o);
                pq[mi][h] += __shfl_xor_sync(0xffffffffu, pq[mi][h], o);
            }
        }
    if (t == 0) {
#pragma unroll
        for (int mi = 0; mi < 2; mi++)
#pragma unroll
            for (int h = 0; h < 2; h++) {
                int rl = wrow + mi * 16 + h * 8 + g;
                red[rl * 4 + (warp & 1) * 2 + 0] = ps[mi][h];
                red[rl * 4 + (warp & 1) * 2 + 1] = pq[mi][h];
            }
    }
    __syncthreads();
#pragma unroll
    for (int mi = 0; mi < 2; mi++)
#pragma unroll
        for (int h = 0; h < 2; h++) {
            int rl = wrow + mi * 16 + h * 8 + g;
            float S = red[rl * 4 + 0] + red[rl * 4 + 2];
            float Q = red[rl * 4 + 1] + red[rl * 4 + 3];
            float mean = S * (1.f / HD);
            float var = Q * (1.f / HD) - mean * mean;
            float rstd = rsqrtf(var + EPS);
            int grow = brow + rl;
            if (grow < NN) {
#pragma unroll
                for (int ni = 0; ni < 8; ni++) {
                    int cbase = wcol + ni * 8 + 2 * t;
                    float v0 = acc[mi][ni][h * 2 + 0];
                    float v1 = acc[mi][ni][h * 2 + 1];
                    float o0 = fmaxf((v0 - mean) * rstd * gamma_s[cbase] + beta_s[cbase], 0.f);
                    float o1 = fmaxf((v1 - mean) * rstd * gamma_s[cbase + 1] + beta_s[cbase + 1], 0.f);
                    if (ext_out) {
                        *(float2*)(ext_out + grow * HD + cbase) = make_float2(o0, o1);
                    } else {
                        *(uint32_t*)(out_h + grow * HD + cbase) = pack2h(o0, o1);
                    }
                }
            }
        }
}

// ---------------- pooling ----------------
__global__ void pool_accum(const float* __restrict__ ne, const int* __restrict__ batch,
                           float* __restrict__ gout) {
    int tx = threadIdx.x;  // 128 = column
    int n0 = blockIdx.x * 128;
    int n1 = min(n0 + 128, NN);
    if (n0 >= NN) return;
    int cur = batch[n0];
    float sum = 0.f, mx = 0.f;
    for (int n = n0; n < n1; n++) {
        int b = batch[n];
        float v = ne[n * HD + tx];
        if (b != cur) {
            atomicAdd(&gout[cur * 256 + tx], sum);
            atomicMax((int*)&gout[cur * 256 + HD + tx], __float_as_int(mx));
            sum = 0.f; mx = 0.f; cur = b;
        }
        sum += v;
        mx = fmaxf(mx, v);
    }
    atomicAdd(&gout[cur * 256 + tx], sum);
    atomicMax((int*)&gout[cur * 256 + HD + tx], __float_as_int(mx));
}
__global__ void finalize_pool(float* __restrict__ gout) {
    int b = blockIdx.x;
    int tx = threadIdx.x;
    gout[b * 256 + tx] /= fmaxf(g_cnt[b], 1.f);
}

// ---------------- launch ----------------
extern "C" void kernel_launch(void* const* d_in, const int* in_sizes, int n_in,
                              void* d_out, int out_size) {
    const float* x   = (const float*)d_in[0];
    const int* ei    = (const int*)d_in[1];
    const int* batch = (const int*)d_in[2];
    const float* W0  = (const float*)d_in[3];
    const float* b0  = (const float*)d_in[4];
    const float* g0  = (const float*)d_in[5];
    const float* be0 = (const float*)d_in[6];
    const float* Wl1 = (const float*)d_in[7];
    const float* bl1 = (const float*)d_in[8];
    const float* Wr1 = (const float*)d_in[9];
    const float* g1  = (const float*)d_in[10];
    const float* be1 = (const float*)d_in[11];
    const float* Wl2 = (const float*)d_in[12];
    const float* bl2 = (const float*)d_in[13];
    const float* Wr2 = (const float*)d_in[14];
    const float* g2  = (const float*)d_in[15];
    const float* be2 = (const float*)d_in[16];
    const float* Wl3 = (const float*)d_in[17];
    const float* bl3 = (const float*)d_in[18];
    const float* Wr3 = (const float*)d_in[19];
    const float* g3  = (const float*)d_in[20];
    const float* be3 = (const float*)d_in[21];

    float* out = (float*)d_out;
    float* ne = out;                           // node_embed (N*H)
    float* gr = out + (size_t)NN * HD;         // graph_embed (B*2H)

    const int* src = ei;
    const int* dst = ei + EE;

    zero_misc<<<NB_SCAN, 256>>>(gr);
    fat_start<<<EMB_BLOCKS + CD_BLOCKS + NB_SCAN, 256>>>(x, W0, b0, g0, be0, dst, batch);
    scan1<<<NB_SCAN, 256>>>();
    scan2<<<1, 512>>>();
    scan3<<<NB_SCAN, 256>>>();
    fill_csr<<<(EE + 255) / 256, 256>>>(src, dst);

    int gemm_blocks = (NN + 127) / 128;
    int agg_blocks = (NN / 2 * 32 + 255) / 256;

    // layer 1: h0 -> h1
    aggregate<<<agg_blocks, 256>>>(0);
    gemm_fused_f16<<<gemm_blocks, 256>>>(0, Wl1, Wr1, bl1, g1, be1, 1, nullptr);
    // layer 2: h1 -> h0
    aggregate<<<agg_blocks, 256>>>(1);
    gemm_fused_f16<<<gemm_blocks, 256>>>(1, Wl2, Wr2, bl2, g2, be2, 0, nullptr);
    // layer 3: h0 -> d_out node region (fp32)
    aggregate<<<agg_blocks, 256>>>(0);
    gemm_fused_f16<<<gemm_blocks, 256>>>(0, Wl3, Wr3, bl3, g3, be3, 0, ne);

    pool_accum<<<(NN + 127) / 128, 128>>>(ne, batch, gr);
    finalize_pool<<<BG, 128>>>(gr);
}